// round 1
// baseline (speedup 1.0000x reference)
#include <cuda_runtime.h>
#include <math.h>

#define S_LEN   2048
#define D_MODEL 2048
#define HD      64
#define NH      32
#define NKV     8
#define KVD     (NKV * HD)   // 512

// Scratch (no allocation allowed in kernel_launch)
__device__ float g_Q[S_LEN * D_MODEL];
__device__ float g_K[S_LEN * KVD];
__device__ float g_V[S_LEN * KVD];
__device__ float g_Y[S_LEN * D_MODEL];

// ---------------------------------------------------------------------------
// Tiled fp32 SGEMM: C[M,N] = A[M,K] * B[K,N]. 64x64 tile, 256 threads, 4x4/thr.
// All dims here are multiples of 64/16 so no bounds checks.
// ---------------------------------------------------------------------------
__global__ void sgemm64(const float* __restrict__ A, const float* __restrict__ B,
                        float* __restrict__ C, int M, int N, int K) {
    __shared__ float As[16][65];   // As[k][m], padded
    __shared__ float Bs[16][64];   // Bs[k][n]

    const int tid = threadIdx.x;
    const int tx = tid & 15;       // n-dir
    const int ty = tid >> 4;       // m-dir
    const int bm = blockIdx.y * 64;
    const int bn = blockIdx.x * 64;

    float acc[4][4];
#pragma unroll
    for (int i = 0; i < 4; i++)
#pragma unroll
        for (int j = 0; j < 4; j++) acc[i][j] = 0.f;

    for (int k0 = 0; k0 < K; k0 += 16) {
#pragma unroll
        for (int i = tid; i < 64 * 16; i += 256) {
            int m  = i >> 4;
            int kk = i & 15;
            As[kk][m] = A[(size_t)(bm + m) * K + k0 + kk];
        }
#pragma unroll
        for (int i = tid; i < 16 * 64; i += 256) {
            int kk = i >> 6;
            int n  = i & 63;
            Bs[kk][n] = B[(size_t)(k0 + kk) * N + bn + n];
        }
        __syncthreads();

#pragma unroll
        for (int kk = 0; kk < 16; kk++) {
            float a[4], b[4];
#pragma unroll
            for (int i = 0; i < 4; i++) a[i] = As[kk][ty * 4 + i];
#pragma unroll
            for (int j = 0; j < 4; j++) b[j] = Bs[kk][tx * 4 + j];
#pragma unroll
            for (int i = 0; i < 4; i++)
#pragma unroll
                for (int j = 0; j < 4; j++) acc[i][j] += a[i] * b[j];
        }
        __syncthreads();
    }

#pragma unroll
    for (int i = 0; i < 4; i++) {
        int m = bm + ty * 4 + i;
#pragma unroll
        for (int j = 0; j < 4; j++) {
            C[(size_t)m * N + bn + tx * 4 + j] = acc[i][j];
        }
    }
}

// ---------------------------------------------------------------------------
// RoPE applied in-place to K and V: pairs (2i, 2i+1) within each head dim.
// cos/sin: [S, HD/2]
// ---------------------------------------------------------------------------
__global__ void rope_kernel(float* __restrict__ K, float* __restrict__ V,
                            const float* __restrict__ cosv,
                            const float* __restrict__ sinv) {
    int idx = blockIdx.x * blockDim.x + threadIdx.x;
    const int total = S_LEN * NKV * (HD / 2);
    if (idx >= total) return;

    int d2 = idx & 31;                 // HD/2 = 32
    int h  = (idx >> 5) & (NKV - 1);   // NKV = 8
    int s  = idx >> 8;                 // / (32*8)

    float c  = cosv[s * 32 + d2];
    float sn = sinv[s * 32 + d2];

    int base = s * KVD + h * HD + 2 * d2;

    float k0 = K[base], k1 = K[base + 1];
    K[base]     = k0 * c - k1 * sn;
    K[base + 1] = k0 * sn + k1 * c;

    float v0 = V[base], v1 = V[base + 1];
    V[base]     = v0 * c - v1 * sn;
    V[base + 1] = v0 * sn + v1 * c;
}

// ---------------------------------------------------------------------------
// Causal flash attention. Grid: (S/64 q-tiles, NH heads). 64 threads/block,
// thread t owns query row q0+t. q and output accumulator in registers,
// K/V tiles + nothing else in smem. Online softmax in fp32.
// Q: [S, NH*HD], K/V: [S, NKV*HD], Y: [S, NH*HD]
// ---------------------------------------------------------------------------
__global__ void attn_kernel(const float* __restrict__ Q, const float* __restrict__ K,
                            const float* __restrict__ V, float* __restrict__ Y) {
    const int h   = blockIdx.y;
    const int q0  = blockIdx.x * 64;
    const int kvh = h >> 2;            // rep = NH/NKV = 4
    const int t   = threadIdx.x;       // 0..63

    __shared__ float ks[64][65];
    __shared__ float vs[64][65];

    // Load q row into registers, pre-scaled by 1/sqrt(hd)
    float q[HD];
#pragma unroll
    for (int d = 0; d < HD; d++)
        q[d] = Q[(size_t)(q0 + t) * D_MODEL + h * HD + d] * 0.125f;

    float m = -1e30f;
    float l = 0.f;
    float acc[HD];
#pragma unroll
    for (int d = 0; d < HD; d++) acc[d] = 0.f;

    float s[64];

    for (int j0 = 0; j0 <= q0; j0 += 64) {
        // Load K/V tile rows j0..j0+63, column t per thread (coalesced)
        for (int r = 0; r < 64; r++) {
            ks[r][t] = K[(size_t)(j0 + r) * KVD + kvh * HD + t];
            vs[r][t] = V[(size_t)(j0 + r) * KVD + kvh * HD + t];
        }
        __syncthreads();

        float mnew = m;
#pragma unroll 4
        for (int kk = 0; kk < 64; kk++) {
            float sacc = 0.f;
#pragma unroll
            for (int d = 0; d < HD; d++) sacc += q[d] * ks[kk][d];
            sacc = (j0 + kk <= q0 + t) ? sacc : -1e30f;
            s[kk] = sacc;
            mnew = fmaxf(mnew, sacc);
        }

        float corr = __expf(m - mnew);
        l *= corr;
#pragma unroll
        for (int d = 0; d < HD; d++) acc[d] *= corr;

#pragma unroll 2
        for (int kk = 0; kk < 64; kk++) {
            float p = __expf(s[kk] - mnew);
            l += p;
#pragma unroll
            for (int d = 0; d < HD; d++) acc[d] += p * vs[kk][d];
        }
        m = mnew;
        __syncthreads();
    }

    float inv_l = 1.0f / l;
#pragma unroll
    for (int d = 0; d < HD; d++)
        Y[(size_t)(q0 + t) * D_MODEL + h * HD + d] = acc[d] * inv_l;
}

// ---------------------------------------------------------------------------
extern "C" void kernel_launch(void* const* d_in, const int* in_sizes, int n_in,
                              void* d_out, int out_size) {
    const float* x    = (const float*)d_in[0];
    const float* tcos = (const float*)d_in[1];
    const float* tsin = (const float*)d_in[2];
    const float* wq   = (const float*)d_in[3];
    const float* wk   = (const float*)d_in[4];
    const float* wv   = (const float*)d_in[5];
    const float* wo   = (const float*)d_in[6];
    float* out = (float*)d_out;

    float *Q, *K, *V, *Y;
    cudaGetSymbolAddress((void**)&Q, g_Q);
    cudaGetSymbolAddress((void**)&K, g_K);
    cudaGetSymbolAddress((void**)&V, g_V);
    cudaGetSymbolAddress((void**)&Y, g_Y);

    // Projections
    sgemm64<<<dim3(D_MODEL / 64, S_LEN / 64), 256>>>(x, wq, Q, S_LEN, D_MODEL, D_MODEL);
    sgemm64<<<dim3(KVD / 64,     S_LEN / 64), 256>>>(x, wk, K, S_LEN, KVD, D_MODEL);
    sgemm64<<<dim3(KVD / 64,     S_LEN / 64), 256>>>(x, wv, V, S_LEN, KVD, D_MODEL);

    // RoPE on K and V
    {
        int total = S_LEN * NKV * (HD / 2);
        rope_kernel<<<(total + 255) / 256, 256>>>(K, V, tcos, tsin);
    }

    // Causal GQA attention
    attn_kernel<<<dim3(S_LEN / 64, NH), 64>>>(Q, K, V, Y);

    // Output projection
    sgemm64<<<dim3(D_MODEL / 64, S_LEN / 64), 256>>>(Y, wo, out, S_LEN, D_MODEL, D_MODEL);
}

// round 2
// speedup vs baseline: 1.1347x; 1.1347x over previous
#include <cuda_runtime.h>
#include <math.h>

#define S_LEN   2048
#define D_MODEL 2048
#define HD      64
#define NH      32
#define NKV     8
#define KVD     (NKV * HD)   // 512

// Scratch (no allocation allowed in kernel_launch)
__device__ float g_Q[S_LEN * D_MODEL];
__device__ float g_K[S_LEN * KVD];
__device__ float g_V[S_LEN * KVD];
__device__ float g_Y[S_LEN * D_MODEL];

// ---------------------------------------------------------------------------
// 128x128x16 fp32 SGEMM, 256 threads, 8x8 microtile, float4 smem traffic.
// M,N multiples of 128; K multiple of 16.
// ---------------------------------------------------------------------------
__global__ __launch_bounds__(256) void sgemm128(
    const float* __restrict__ A, const float* __restrict__ B,
    float* __restrict__ C, int M, int N, int K) {

    __shared__ float As[16][132];   // [k][m], padded to kill store conflicts
    __shared__ float Bs[16][128];   // [k][n]

    const int tid = threadIdx.x;
    const int tx  = tid & 15;        // n-dir (8 cols each)
    const int ty  = tid >> 4;        // m-dir (8 rows each)
    const int bm  = blockIdx.y * 128;
    const int bn  = blockIdx.x * 128;

    // A-load mapping: 128 rows x 16 k-cols = 2048 floats / 256 thr = 2 float4
    const int arow = tid >> 2;           // 0..63
    const int acol = (tid & 3) * 4;      // 0,4,8,12
    // B-load mapping: 16 k-rows x 128 cols
    const int brow = tid >> 5;           // 0..7
    const int bcol = (tid & 31) * 4;     // 0..124

    float acc[8][8];
#pragma unroll
    for (int i = 0; i < 8; i++)
#pragma unroll
        for (int j = 0; j < 8; j++) acc[i][j] = 0.f;

    for (int k0 = 0; k0 < K; k0 += 16) {
        float4 a0 = *(const float4*)&A[(size_t)(bm + arow)      * K + k0 + acol];
        float4 a1 = *(const float4*)&A[(size_t)(bm + arow + 64) * K + k0 + acol];
        As[acol + 0][arow] = a0.x;  As[acol + 1][arow] = a0.y;
        As[acol + 2][arow] = a0.z;  As[acol + 3][arow] = a0.w;
        As[acol + 0][arow + 64] = a1.x;  As[acol + 1][arow + 64] = a1.y;
        As[acol + 2][arow + 64] = a1.z;  As[acol + 3][arow + 64] = a1.w;

        *(float4*)&Bs[brow    ][bcol] = *(const float4*)&B[(size_t)(k0 + brow    ) * N + bn + bcol];
        *(float4*)&Bs[brow + 8][bcol] = *(const float4*)&B[(size_t)(k0 + brow + 8) * N + bn + bcol];
        __syncthreads();

#pragma unroll
        for (int kk = 0; kk < 16; kk++) {
            float a[8], b[8];
            *(float4*)(a)     = *(const float4*)&As[kk][ty * 8];
            *(float4*)(a + 4) = *(const float4*)&As[kk][ty * 8 + 4];
            *(float4*)(b)     = *(const float4*)&Bs[kk][tx * 8];
            *(float4*)(b + 4) = *(const float4*)&Bs[kk][tx * 8 + 4];
#pragma unroll
            for (int i = 0; i < 8; i++)
#pragma unroll
                for (int j = 0; j < 8; j++) acc[i][j] += a[i] * b[j];
        }
        __syncthreads();
    }

#pragma unroll
    for (int i = 0; i < 8; i++) {
        size_t r = (size_t)(bm + ty * 8 + i) * N + bn + tx * 8;
        *(float4*)&C[r]     = *(float4*)&acc[i][0];
        *(float4*)&C[r + 4] = *(float4*)&acc[i][4];
    }
}

// ---------------------------------------------------------------------------
// 64x64 tile SGEMM for the skinny K/V projections (N=512 -> 256 blocks).
// ---------------------------------------------------------------------------
__global__ void sgemm64(const float* __restrict__ A, const float* __restrict__ B,
                        float* __restrict__ C, int M, int N, int K) {
    __shared__ float As[16][65];
    __shared__ float Bs[16][64];

    const int tid = threadIdx.x;
    const int tx = tid & 15;
    const int ty = tid >> 4;
    const int bm = blockIdx.y * 64;
    const int bn = blockIdx.x * 64;

    float acc[4][4];
#pragma unroll
    for (int i = 0; i < 4; i++)
#pragma unroll
        for (int j = 0; j < 4; j++) acc[i][j] = 0.f;

    for (int k0 = 0; k0 < K; k0 += 16) {
#pragma unroll
        for (int i = tid; i < 64 * 16; i += 256) {
            int m  = i >> 4;
            int kk = i & 15;
            As[kk][m] = A[(size_t)(bm + m) * K + k0 + kk];
        }
#pragma unroll
        for (int i = tid; i < 16 * 64; i += 256) {
            int kk = i >> 6;
            int n  = i & 63;
            Bs[kk][n] = B[(size_t)(k0 + kk) * N + bn + n];
        }
        __syncthreads();

#pragma unroll
        for (int kk = 0; kk < 16; kk++) {
            float a[4], b[4];
#pragma unroll
            for (int i = 0; i < 4; i++) a[i] = As[kk][ty * 4 + i];
#pragma unroll
            for (int j = 0; j < 4; j++) b[j] = Bs[kk][tx * 4 + j];
#pragma unroll
            for (int i = 0; i < 4; i++)
#pragma unroll
                for (int j = 0; j < 4; j++) acc[i][j] += a[i] * b[j];
        }
        __syncthreads();
    }

#pragma unroll
    for (int i = 0; i < 4; i++) {
        int m = bm + ty * 4 + i;
#pragma unroll
        for (int j = 0; j < 4; j++) {
            C[(size_t)m * N + bn + tx * 4 + j] = acc[i][j];
        }
    }
}

// ---------------------------------------------------------------------------
// RoPE in-place on K and V.
// ---------------------------------------------------------------------------
__global__ void rope_kernel(float* __restrict__ K, float* __restrict__ V,
                            const float* __restrict__ cosv,
                            const float* __restrict__ sinv) {
    int idx = blockIdx.x * blockDim.x + threadIdx.x;
    const int total = S_LEN * NKV * (HD / 2);
    if (idx >= total) return;

    int d2 = idx & 31;
    int h  = (idx >> 5) & (NKV - 1);
    int s  = idx >> 8;

    float c  = cosv[s * 32 + d2];
    float sn = sinv[s * 32 + d2];

    int base = s * KVD + h * HD + 2 * d2;

    float k0 = K[base], k1 = K[base + 1];
    K[base]     = k0 * c - k1 * sn;
    K[base + 1] = k0 * sn + k1 * c;

    float v0 = V[base], v1 = V[base + 1];
    V[base]     = v0 * c - v1 * sn;
    V[base + 1] = v0 * sn + v1 * c;
}

// ---------------------------------------------------------------------------
// Causal flash attention, GQA. Grid: (S/64, NH). 128 threads per block.
// A thread PAIR owns one query row; each thread of the pair owns 32 of the
// 64 head dims. Dot products are completed with one shfl_xor. No spills.
// ---------------------------------------------------------------------------
__global__ __launch_bounds__(128) void attn_kernel(
    const float* __restrict__ Q, const float* __restrict__ K,
    const float* __restrict__ V, float* __restrict__ Y) {

    const int h    = blockIdx.y;
    const int q0   = blockIdx.x * 64;
    const int kvh  = h >> 2;           // rep = 4
    const int t    = threadIdx.x;      // 0..127
    const int row  = t >> 1;           // 0..63
    const int half = t & 1;            // which 32 dims
    const int dbase = half * 32;

    __shared__ float ks[64][65];
    __shared__ float vs[64][65];

    float q[32];
#pragma unroll
    for (int i = 0; i < 32; i++)
        q[i] = Q[(size_t)(q0 + row) * D_MODEL + h * HD + dbase + i] * 0.125f;

    float m = -1e30f;
    float l = 0.f;
    float acc[32];
#pragma unroll
    for (int i = 0; i < 32; i++) acc[i] = 0.f;

    float s[64];

    for (int j0 = 0; j0 <= q0; j0 += 64) {
        // Stage K (threads 0-63) and V (threads 64-127) tiles, coalesced.
        {
            int c = t & 63;
            if (t < 64) {
#pragma unroll 4
                for (int r = 0; r < 64; r++)
                    ks[r][c] = K[(size_t)(j0 + r) * KVD + kvh * HD + c];
            } else {
#pragma unroll 4
                for (int r = 0; r < 64; r++)
                    vs[r][c] = V[(size_t)(j0 + r) * KVD + kvh * HD + c];
            }
        }
        __syncthreads();

        float mnew = m;
#pragma unroll 2
        for (int kk = 0; kk < 64; kk++) {
            float part = 0.f;
#pragma unroll
            for (int i = 0; i < 32; i++) part += q[i] * ks[kk][dbase + i];
            float sc = part + __shfl_xor_sync(0xffffffffu, part, 1);
            sc = (j0 + kk <= q0 + row) ? sc : -1e30f;
            s[kk] = sc;
            mnew = fmaxf(mnew, sc);
        }

        float corr = __expf(m - mnew);
        l *= corr;
#pragma unroll
        for (int i = 0; i < 32; i++) acc[i] *= corr;

#pragma unroll 2
        for (int kk = 0; kk < 64; kk++) {
            float p = __expf(s[kk] - mnew);
            l += p;
#pragma unroll
            for (int i = 0; i < 32; i++) acc[i] += p * vs[kk][dbase + i];
        }
        m = mnew;
        __syncthreads();
    }

    float inv_l = 1.0f / l;
#pragma unroll
    for (int i = 0; i < 32; i++)
        Y[(size_t)(q0 + row) * D_MODEL + h * HD + dbase + i] = acc[i] * inv_l;
}

// ---------------------------------------------------------------------------
extern "C" void kernel_launch(void* const* d_in, const int* in_sizes, int n_in,
                              void* d_out, int out_size) {
    const float* x    = (const float*)d_in[0];
    const float* tcos = (const float*)d_in[1];
    const float* tsin = (const float*)d_in[2];
    const float* wq   = (const float*)d_in[3];
    const float* wk   = (const float*)d_in[4];
    const float* wv   = (const float*)d_in[5];
    const float* wo   = (const float*)d_in[6];
    float* out = (float*)d_out;

    float *Q, *K, *V, *Y;
    cudaGetSymbolAddress((void**)&Q, g_Q);
    cudaGetSymbolAddress((void**)&K, g_K);
    cudaGetSymbolAddress((void**)&V, g_V);
    cudaGetSymbolAddress((void**)&Y, g_Y);

    // Projections
    sgemm128<<<dim3(D_MODEL / 128, S_LEN / 128), 256>>>(x, wq, Q, S_LEN, D_MODEL, D_MODEL);
    sgemm64 <<<dim3(KVD / 64,      S_LEN / 64),  256>>>(x, wk, K, S_LEN, KVD, D_MODEL);
    sgemm64 <<<dim3(KVD / 64,      S_LEN / 64),  256>>>(x, wv, V, S_LEN, KVD, D_MODEL);

    // RoPE on K and V
    {
        int total = S_LEN * NKV * (HD / 2);
        rope_kernel<<<(total + 255) / 256, 256>>>(K, V, tcos, tsin);
    }

    // Causal GQA attention
    attn_kernel<<<dim3(S_LEN / 64, NH), 128>>>(Q, K, V, Y);

    // Output projection
    sgemm128<<<dim3(D_MODEL / 128, S_LEN / 128), 256>>>(Y, wo, out, S_LEN, D_MODEL, D_MODEL);
}

// round 4
// speedup vs baseline: 1.4592x; 1.2860x over previous
#include <cuda_runtime.h>
#include <cuda_bf16.h>
#include <stdint.h>
#include <math.h>

#define S_LEN   2048
#define D_MODEL 2048
#define HD      64
#define NH      32
#define NKV     8
#define KVD     (NKV * HD)   // 512

// ---------------------------------------------------------------------------
// Scratch (__device__ globals; no allocation allowed)
// ---------------------------------------------------------------------------
__device__ float g_Q[S_LEN * D_MODEL];
__device__ float g_K[S_LEN * KVD];
__device__ float g_V[S_LEN * KVD];
__device__ float g_Y[S_LEN * D_MODEL];

__device__ __nv_bfloat16 g_xhi[S_LEN * D_MODEL], g_xlo[S_LEN * D_MODEL];
__device__ __nv_bfloat16 g_yhi[S_LEN * D_MODEL], g_ylo[S_LEN * D_MODEL];
__device__ __nv_bfloat16 g_wqT_hi[D_MODEL * D_MODEL], g_wqT_lo[D_MODEL * D_MODEL];
__device__ __nv_bfloat16 g_woT_hi[D_MODEL * D_MODEL], g_woT_lo[D_MODEL * D_MODEL];
__device__ __nv_bfloat16 g_wkT_hi[KVD * D_MODEL],     g_wkT_lo[KVD * D_MODEL];
__device__ __nv_bfloat16 g_wvT_hi[KVD * D_MODEL],     g_wvT_lo[KVD * D_MODEL];

// ---------------------------------------------------------------------------
// Portable tensor-core mma (sm_80+, works on plain sm_103 target):
// D[16x8] += A[16x16] * B[16x8], bf16 in, fp32 acc.
// ---------------------------------------------------------------------------
__device__ __forceinline__ void mma16816(float* c, const uint32_t* a, const uint32_t* b) {
    asm volatile(
        "mma.sync.aligned.m16n8k16.row.col.f32.bf16.bf16.f32 "
        "{%0,%1,%2,%3}, {%4,%5,%6,%7}, {%8,%9}, {%0,%1,%2,%3};"
        : "+f"(c[0]), "+f"(c[1]), "+f"(c[2]), "+f"(c[3])
        : "r"(a[0]), "r"(a[1]), "r"(a[2]), "r"(a[3]), "r"(b[0]), "r"(b[1]));
}

// ---------------------------------------------------------------------------
// Split fp32 -> bf16 hi + lo
// ---------------------------------------------------------------------------
__global__ void split_kernel(const float* __restrict__ src,
                             __nv_bfloat16* __restrict__ hi,
                             __nv_bfloat16* __restrict__ lo, int n) {
    int i = blockIdx.x * 256 + threadIdx.x;
    if (i >= n) return;
    float v = src[i];
    __nv_bfloat16 h = __float2bfloat16(v);
    hi[i] = h;
    lo[i] = __float2bfloat16(v - __bfloat162float(h));
}

// ---------------------------------------------------------------------------
// Transpose + split: W[Kd][Nd] fp32 -> WT[Nd][Kd] bf16 hi/lo
// ---------------------------------------------------------------------------
__global__ void transpose_split_kernel(const float* __restrict__ W,
                                       __nv_bfloat16* __restrict__ Thi,
                                       __nv_bfloat16* __restrict__ Tlo,
                                       int Kd, int Nd) {
    __shared__ float t[32][33];
    int bx = blockIdx.x * 32;   // n
    int by = blockIdx.y * 32;   // k
    int tx = threadIdx.x, ty = threadIdx.y;   // 32 x 8
#pragma unroll
    for (int j = 0; j < 32; j += 8)
        t[ty + j][tx] = W[(size_t)(by + ty + j) * Nd + bx + tx];
    __syncthreads();
#pragma unroll
    for (int j = 0; j < 32; j += 8) {
        int n = bx + ty + j, k = by + tx;
        float v = t[tx][ty + j];
        __nv_bfloat16 h = __float2bfloat16(v);
        Thi[(size_t)n * Kd + k] = h;
        Tlo[(size_t)n * Kd + k] = __float2bfloat16(v - __bfloat162float(h));
    }
}

// ---------------------------------------------------------------------------
// Warp-MMA GEMM, split-bf16 x3: C[M,N] = (Ahi+Alo)[M,K] * (Bhi+Blo)[N,K]^T
// Block 128x128, 256 thr = 8 warps (4x2), warp tile 32x64.
// K-chunks of 32 staged in smem (stride 40 bf16 -> conflict-free frag loads).
// ---------------------------------------------------------------------------
#define SA 40   // padded smem row stride in bf16 elements

__global__ __launch_bounds__(256) void gemm_mma_x3(
    const __nv_bfloat16* __restrict__ Ahi, const __nv_bfloat16* __restrict__ Alo,
    const __nv_bfloat16* __restrict__ Bhi, const __nv_bfloat16* __restrict__ Blo,
    float* __restrict__ C, int N, int Kd) {

    __shared__ __nv_bfloat16 sAh[128 * SA], sAl[128 * SA];
    __shared__ __nv_bfloat16 sBh[128 * SA], sBl[128 * SA];

    const int tid  = threadIdx.x;
    const int lane = tid & 31;
    const int wid  = tid >> 5;
    const int wm   = (wid >> 1) * 32;   // warp row offset in tile
    const int wn   = (wid & 1) * 64;    // warp col offset in tile
    const int bm   = blockIdx.y * 128;
    const int bn   = blockIdx.x * 128;

    float acc[2][8][4];
#pragma unroll
    for (int i = 0; i < 2; i++)
#pragma unroll
        for (int j = 0; j < 8; j++)
#pragma unroll
            for (int k = 0; k < 4; k++) acc[i][j][k] = 0.f;

    // global->smem mapping: each thread moves 2 rows x 16B per tile
    const int lrow = tid >> 2;          // 0..63
    const int lcb  = (tid & 3) * 16;    // byte offset in 64B row chunk

    const int grp = lane >> 2;          // 0..7
    const int qd  = (lane & 3) * 2;     // 0,2,4,6

    for (int k0 = 0; k0 < Kd; k0 += 32) {
        // Stage 4 tiles (128 rows x 32 bf16 each)
#pragma unroll
        for (int rr = 0; rr < 2; rr++) {
            int row = lrow + rr * 64;
            size_t goff = (size_t)(bm + row) * Kd + k0;
            size_t boff = (size_t)(bn + row) * Kd + k0;
            uint32_t soff = row * (SA * 2) + lcb;
            *(uint4*)((char*)sAh + soff) = *(const uint4*)((const char*)(Ahi + goff) + lcb);
            *(uint4*)((char*)sAl + soff) = *(const uint4*)((const char*)(Alo + goff) + lcb);
            *(uint4*)((char*)sBh + soff) = *(const uint4*)((const char*)(Bhi + boff) + lcb);
            *(uint4*)((char*)sBl + soff) = *(const uint4*)((const char*)(Blo + boff) + lcb);
        }
        __syncthreads();

#pragma unroll
        for (int ks = 0; ks < 2; ks++) {
            const int kc = ks * 16;

            uint32_t ah[2][4], al[2][4];
#pragma unroll
            for (int mt = 0; mt < 2; mt++) {
                int r = wm + mt * 16 + grp;
                int c = kc + qd;
                ah[mt][0] = *(const uint32_t*)&sAh[r * SA + c];
                ah[mt][1] = *(const uint32_t*)&sAh[(r + 8) * SA + c];
                ah[mt][2] = *(const uint32_t*)&sAh[r * SA + c + 8];
                ah[mt][3] = *(const uint32_t*)&sAh[(r + 8) * SA + c + 8];
                al[mt][0] = *(const uint32_t*)&sAl[r * SA + c];
                al[mt][1] = *(const uint32_t*)&sAl[(r + 8) * SA + c];
                al[mt][2] = *(const uint32_t*)&sAl[r * SA + c + 8];
                al[mt][3] = *(const uint32_t*)&sAl[(r + 8) * SA + c + 8];
            }

            uint32_t bh[8][2], bl[8][2];
#pragma unroll
            for (int nt = 0; nt < 8; nt++) {
                int n = wn + nt * 8 + grp;
                int c = kc + qd;
                bh[nt][0] = *(const uint32_t*)&sBh[n * SA + c];
                bh[nt][1] = *(const uint32_t*)&sBh[n * SA + c + 8];
                bl[nt][0] = *(const uint32_t*)&sBl[n * SA + c];
                bl[nt][1] = *(const uint32_t*)&sBl[n * SA + c + 8];
            }

#pragma unroll
            for (int mt = 0; mt < 2; mt++)
#pragma unroll
                for (int nt = 0; nt < 8; nt++) {
                    mma16816(acc[mt][nt], ah[mt], bh[nt]);
                    mma16816(acc[mt][nt], ah[mt], bl[nt]);
                    mma16816(acc[mt][nt], al[mt], bh[nt]);
                }
        }
        __syncthreads();
    }

    // Epilogue
#pragma unroll
    for (int mt = 0; mt < 2; mt++) {
        int r = bm + wm + mt * 16 + grp;
#pragma unroll
        for (int nt = 0; nt < 8; nt++) {
            int cc = bn + wn + nt * 8 + qd;
            *(float2*)&C[(size_t)r * N + cc]       = make_float2(acc[mt][nt][0], acc[mt][nt][1]);
            *(float2*)&C[(size_t)(r + 8) * N + cc] = make_float2(acc[mt][nt][2], acc[mt][nt][3]);
        }
    }
}

// ---------------------------------------------------------------------------
// RoPE in-place on K and V.
// ---------------------------------------------------------------------------
__global__ void rope_kernel(float* __restrict__ K, float* __restrict__ V,
                            const float* __restrict__ cosv,
                            const float* __restrict__ sinv) {
    int idx = blockIdx.x * blockDim.x + threadIdx.x;
    const int total = S_LEN * NKV * (HD / 2);
    if (idx >= total) return;

    int d2 = idx & 31;
    int h  = (idx >> 5) & (NKV - 1);
    int s  = idx >> 8;

    float c  = cosv[s * 32 + d2];
    float sn = sinv[s * 32 + d2];

    int base = s * KVD + h * HD + 2 * d2;

    float k0 = K[base], k1 = K[base + 1];
    K[base]     = k0 * c - k1 * sn;
    K[base + 1] = k0 * sn + k1 * c;

    float v0 = V[base], v1 = V[base + 1];
    V[base]     = v0 * c - v1 * sn;
    V[base + 1] = v0 * sn + v1 * c;
}

// ---------------------------------------------------------------------------
// Causal flash attention, GQA (fp32 SIMT). Grid: (S/64, NH). 128 thr/block.
// Thread PAIR owns one query row; each thread owns 32 of the 64 head dims.
// ---------------------------------------------------------------------------
__global__ __launch_bounds__(128) void attn_kernel(
    const float* __restrict__ Q, const float* __restrict__ K,
    const float* __restrict__ V, float* __restrict__ Y) {

    const int h    = blockIdx.y;
    const int q0   = blockIdx.x * 64;
    const int kvh  = h >> 2;           // rep = 4
    const int t    = threadIdx.x;      // 0..127
    const int row  = t >> 1;           // 0..63
    const int half = t & 1;
    const int dbase = half * 32;

    __shared__ float ks[64][65];
    __shared__ float vs[64][65];

    float q[32];
#pragma unroll
    for (int i = 0; i < 32; i++)
        q[i] = Q[(size_t)(q0 + row) * D_MODEL + h * HD + dbase + i] * 0.125f;

    float m = -1e30f;
    float l = 0.f;
    float acc[32];
#pragma unroll
    for (int i = 0; i < 32; i++) acc[i] = 0.f;

    float s[64];

    for (int j0 = 0; j0 <= q0; j0 += 64) {
        {
            int c = t & 63;
            if (t < 64) {
#pragma unroll 4
                for (int r = 0; r < 64; r++)
                    ks[r][c] = K[(size_t)(j0 + r) * KVD + kvh * HD + c];
            } else {
#pragma unroll 4
                for (int r = 0; r < 64; r++)
                    vs[r][c] = V[(size_t)(j0 + r) * KVD + kvh * HD + c];
            }
        }
        __syncthreads();

        float mnew = m;
#pragma unroll 2
        for (int kk = 0; kk < 64; kk++) {
            float part = 0.f;
#pragma unroll
            for (int i = 0; i < 32; i++) part += q[i] * ks[kk][dbase + i];
            float sc = part + __shfl_xor_sync(0xffffffffu, part, 1);
            sc = (j0 + kk <= q0 + row) ? sc : -1e30f;
            s[kk] = sc;
            mnew = fmaxf(mnew, sc);
        }

        float corr = __expf(m - mnew);
        l *= corr;
#pragma unroll
        for (int i = 0; i < 32; i++) acc[i] *= corr;

#pragma unroll 2
        for (int kk = 0; kk < 64; kk++) {
            float p = __expf(s[kk] - mnew);
            l += p;
#pragma unroll
            for (int i = 0; i < 32; i++) acc[i] += p * vs[kk][dbase + i];
        }
        m = mnew;
        __syncthreads();
    }

    float inv_l = 1.0f / l;
#pragma unroll
    for (int i = 0; i < 32; i++)
        Y[(size_t)(q0 + row) * D_MODEL + h * HD + dbase + i] = acc[i] * inv_l;
}

// ---------------------------------------------------------------------------
extern "C" void kernel_launch(void* const* d_in, const int* in_sizes, int n_in,
                              void* d_out, int out_size) {
    const float* x    = (const float*)d_in[0];
    const float* tcos = (const float*)d_in[1];
    const float* tsin = (const float*)d_in[2];
    const float* wq   = (const float*)d_in[3];
    const float* wk   = (const float*)d_in[4];
    const float* wv   = (const float*)d_in[5];
    const float* wo   = (const float*)d_in[6];
    float* out = (float*)d_out;

    float *Q, *K, *V, *Y;
    cudaGetSymbolAddress((void**)&Q, g_Q);
    cudaGetSymbolAddress((void**)&K, g_K);
    cudaGetSymbolAddress((void**)&V, g_V);
    cudaGetSymbolAddress((void**)&Y, g_Y);

    __nv_bfloat16 *xhi, *xlo, *yhi, *ylo;
    __nv_bfloat16 *wqThi, *wqTlo, *wkThi, *wkTlo, *wvThi, *wvTlo, *woThi, *woTlo;
    cudaGetSymbolAddress((void**)&xhi, g_xhi);   cudaGetSymbolAddress((void**)&xlo, g_xlo);
    cudaGetSymbolAddress((void**)&yhi, g_yhi);   cudaGetSymbolAddress((void**)&ylo, g_ylo);
    cudaGetSymbolAddress((void**)&wqThi, g_wqT_hi); cudaGetSymbolAddress((void**)&wqTlo, g_wqT_lo);
    cudaGetSymbolAddress((void**)&wkThi, g_wkT_hi); cudaGetSymbolAddress((void**)&wkTlo, g_wkT_lo);
    cudaGetSymbolAddress((void**)&wvThi, g_wvT_hi); cudaGetSymbolAddress((void**)&wvTlo, g_wvT_lo);
    cudaGetSymbolAddress((void**)&woThi, g_woT_hi); cudaGetSymbolAddress((void**)&woTlo, g_woT_lo);

    const int nx = S_LEN * D_MODEL;

    // Split x into bf16 hi/lo
    split_kernel<<<(nx + 255) / 256, 256>>>(x, xhi, xlo, nx);

    // Transpose+split weights: W[K][N] -> WT[N][K]
    transpose_split_kernel<<<dim3(D_MODEL / 32, D_MODEL / 32), dim3(32, 8)>>>(wq, wqThi, wqTlo, D_MODEL, D_MODEL);
    transpose_split_kernel<<<dim3(KVD / 32,     D_MODEL / 32), dim3(32, 8)>>>(wk, wkThi, wkTlo, D_MODEL, KVD);
    transpose_split_kernel<<<dim3(KVD / 32,     D_MODEL / 32), dim3(32, 8)>>>(wv, wvThi, wvTlo, D_MODEL, KVD);
    transpose_split_kernel<<<dim3(D_MODEL / 32, D_MODEL / 32), dim3(32, 8)>>>(wo, woThi, woTlo, D_MODEL, D_MODEL);

    // Projections on tensor cores (mma.sync)
    gemm_mma_x3<<<dim3(D_MODEL / 128, S_LEN / 128), 256>>>(xhi, xlo, wqThi, wqTlo, Q, D_MODEL, D_MODEL);
    gemm_mma_x3<<<dim3(KVD / 128,     S_LEN / 128), 256>>>(xhi, xlo, wkThi, wkTlo, K, KVD, D_MODEL);
    gemm_mma_x3<<<dim3(KVD / 128,     S_LEN / 128), 256>>>(xhi, xlo, wvThi, wvTlo, V, KVD, D_MODEL);

    // RoPE on K and V
    {
        int total = S_LEN * NKV * (HD / 2);
        rope_kernel<<<(total + 255) / 256, 256>>>(K, V, tcos, tsin);
    }

    // Causal GQA attention (fp32)
    attn_kernel<<<dim3(S_LEN / 64, NH), 128>>>(Q, K, V, Y);

    // Split Y and output projection
    split_kernel<<<(nx + 255) / 256, 256>>>(Y, yhi, ylo, nx);
    gemm_mma_x3<<<dim3(D_MODEL / 128, S_LEN / 128), 256>>>(yhi, ylo, woThi, woTlo, out, D_MODEL, D_MODEL);
}

// round 6
// speedup vs baseline: 3.2428x; 2.2224x over previous
#include <cuda_runtime.h>
#include <cuda_bf16.h>
#include <stdint.h>
#include <math.h>

#define S_LEN   2048
#define D_MODEL 2048
#define HD      64
#define NH      32
#define NKV     8
#define KVD     (NKV * HD)   // 512

// ---------------------------------------------------------------------------
// Scratch (__device__ globals; no allocation allowed)
// ---------------------------------------------------------------------------
__device__ float g_Q[S_LEN * D_MODEL];
__device__ float g_K[S_LEN * KVD];
__device__ float g_V[S_LEN * KVD];

__device__ __nv_bfloat16 g_xhi[S_LEN * D_MODEL], g_xlo[S_LEN * D_MODEL];
__device__ __nv_bfloat16 g_yhi[S_LEN * D_MODEL], g_ylo[S_LEN * D_MODEL];
__device__ __nv_bfloat16 g_qhi[S_LEN * D_MODEL], g_qlo[S_LEN * D_MODEL];
__device__ __nv_bfloat16 g_khi[S_LEN * KVD],     g_klo[S_LEN * KVD];
__device__ __nv_bfloat16 g_vthi[KVD * S_LEN],    g_vtlo[KVD * S_LEN];
__device__ __nv_bfloat16 g_wqT_hi[D_MODEL * D_MODEL], g_wqT_lo[D_MODEL * D_MODEL];
__device__ __nv_bfloat16 g_woT_hi[D_MODEL * D_MODEL], g_woT_lo[D_MODEL * D_MODEL];
__device__ __nv_bfloat16 g_wkT_hi[KVD * D_MODEL],     g_wkT_lo[KVD * D_MODEL];
__device__ __nv_bfloat16 g_wvT_hi[KVD * D_MODEL],     g_wvT_lo[KVD * D_MODEL];

// ---------------------------------------------------------------------------
// mma.sync m16n8k16 bf16 (portable, works on plain sm_103 target)
// ---------------------------------------------------------------------------
__device__ __forceinline__ void mma16816(float* c, const uint32_t* a, const uint32_t* b) {
    asm volatile(
        "mma.sync.aligned.m16n8k16.row.col.f32.bf16.bf16.f32 "
        "{%0,%1,%2,%3}, {%4,%5,%6,%7}, {%8,%9}, {%0,%1,%2,%3};"
        : "+f"(c[0]), "+f"(c[1]), "+f"(c[2]), "+f"(c[3])
        : "r"(a[0]), "r"(a[1]), "r"(a[2]), "r"(a[3]), "r"(b[0]), "r"(b[1]));
}

__device__ __forceinline__ uint32_t pack_bf16x2(float lo, float hi) {
    __nv_bfloat162 t = __floats2bfloat162_rn(lo, hi);   // .x = lo half
    return *reinterpret_cast<uint32_t*>(&t);
}
__device__ __forceinline__ float2 unpack_bf16x2(uint32_t u) {
    __nv_bfloat162 t = *reinterpret_cast<__nv_bfloat162*>(&u);
    return make_float2(__bfloat162float(t.x), __bfloat162float(t.y));
}

// ---------------------------------------------------------------------------
// Split fp32 -> bf16 hi + lo (optional scale applied first)
// ---------------------------------------------------------------------------
__global__ void split_kernel(const float* __restrict__ src,
                             __nv_bfloat16* __restrict__ hi,
                             __nv_bfloat16* __restrict__ lo, int n, float scale) {
    int i = blockIdx.x * 256 + threadIdx.x;
    if (i >= n) return;
    float v = src[i] * scale;
    __nv_bfloat16 h = __float2bfloat16(v);
    hi[i] = h;
    lo[i] = __float2bfloat16(v - __bfloat162float(h));
}

// ---------------------------------------------------------------------------
// Transpose + split: W[rows][Nd] fp32 -> WT[Nd][rows] bf16 hi/lo
// (out stride = Kd param). Grid (Nd/32, rows/32), block (32,8).
// ---------------------------------------------------------------------------
__global__ void transpose_split_kernel(const float* __restrict__ W,
                                       __nv_bfloat16* __restrict__ Thi,
                                       __nv_bfloat16* __restrict__ Tlo,
                                       int Kd, int Nd) {
    __shared__ float t[32][33];
    int bx = blockIdx.x * 32;   // n
    int by = blockIdx.y * 32;   // k
    int tx = threadIdx.x, ty = threadIdx.y;
#pragma unroll
    for (int j = 0; j < 32; j += 8)
        t[ty + j][tx] = W[(size_t)(by + ty + j) * Nd + bx + tx];
    __syncthreads();
#pragma unroll
    for (int j = 0; j < 32; j += 8) {
        int n = bx + ty + j, k = by + tx;
        float v = t[tx][ty + j];
        __nv_bfloat16 h = __float2bfloat16(v);
        Thi[(size_t)n * Kd + k] = h;
        Tlo[(size_t)n * Kd + k] = __float2bfloat16(v - __bfloat162float(h));
    }
}

// ---------------------------------------------------------------------------
// Warp-MMA GEMM, split-bf16 x3: C = (Ahi+Alo)[M,K] * (Bhi+Blo)[N,K]^T
// ---------------------------------------------------------------------------
#define SA 40

__global__ __launch_bounds__(256) void gemm_mma_x3(
    const __nv_bfloat16* __restrict__ Ahi, const __nv_bfloat16* __restrict__ Alo,
    const __nv_bfloat16* __restrict__ Bhi, const __nv_bfloat16* __restrict__ Blo,
    float* __restrict__ C, int N, int Kd) {

    __shared__ __nv_bfloat16 sAh[128 * SA], sAl[128 * SA];
    __shared__ __nv_bfloat16 sBh[128 * SA], sBl[128 * SA];

    const int tid  = threadIdx.x;
    const int lane = tid & 31;
    const int wid  = tid >> 5;
    const int wm   = (wid >> 1) * 32;
    const int wn   = (wid & 1) * 64;
    const int bm   = blockIdx.y * 128;
    const int bn   = blockIdx.x * 128;

    float acc[2][8][4];
#pragma unroll
    for (int i = 0; i < 2; i++)
#pragma unroll
        for (int j = 0; j < 8; j++)
#pragma unroll
            for (int k = 0; k < 4; k++) acc[i][j][k] = 0.f;

    const int lrow = tid >> 2;
    const int lcb  = (tid & 3) * 16;
    const int grp = lane >> 2;
    const int qd  = (lane & 3) * 2;

    for (int k0 = 0; k0 < Kd; k0 += 32) {
#pragma unroll
        for (int rr = 0; rr < 2; rr++) {
            int row = lrow + rr * 64;
            size_t goff = (size_t)(bm + row) * Kd + k0;
            size_t boff = (size_t)(bn + row) * Kd + k0;
            uint32_t soff = row * (SA * 2) + lcb;
            *(uint4*)((char*)sAh + soff) = *(const uint4*)((const char*)(Ahi + goff) + lcb);
            *(uint4*)((char*)sAl + soff) = *(const uint4*)((const char*)(Alo + goff) + lcb);
            *(uint4*)((char*)sBh + soff) = *(const uint4*)((const char*)(Bhi + boff) + lcb);
            *(uint4*)((char*)sBl + soff) = *(const uint4*)((const char*)(Blo + boff) + lcb);
        }
        __syncthreads();

#pragma unroll
        for (int ks = 0; ks < 2; ks++) {
            const int kc = ks * 16;
            uint32_t ah[2][4], al[2][4];
#pragma unroll
            for (int mt = 0; mt < 2; mt++) {
                int r = wm + mt * 16 + grp;
                int c = kc + qd;
                ah[mt][0] = *(const uint32_t*)&sAh[r * SA + c];
                ah[mt][1] = *(const uint32_t*)&sAh[(r + 8) * SA + c];
                ah[mt][2] = *(const uint32_t*)&sAh[r * SA + c + 8];
                ah[mt][3] = *(const uint32_t*)&sAh[(r + 8) * SA + c + 8];
                al[mt][0] = *(const uint32_t*)&sAl[r * SA + c];
                al[mt][1] = *(const uint32_t*)&sAl[(r + 8) * SA + c];
                al[mt][2] = *(const uint32_t*)&sAl[r * SA + c + 8];
                al[mt][3] = *(const uint32_t*)&sAl[(r + 8) * SA + c + 8];
            }
            uint32_t bh[8][2], bl[8][2];
#pragma unroll
            for (int nt = 0; nt < 8; nt++) {
                int n = wn + nt * 8 + grp;
                int c = kc + qd;
                bh[nt][0] = *(const uint32_t*)&sBh[n * SA + c];
                bh[nt][1] = *(const uint32_t*)&sBh[n * SA + c + 8];
                bl[nt][0] = *(const uint32_t*)&sBl[n * SA + c];
                bl[nt][1] = *(const uint32_t*)&sBl[n * SA + c + 8];
            }
#pragma unroll
            for (int mt = 0; mt < 2; mt++)
#pragma unroll
                for (int nt = 0; nt < 8; nt++) {
                    mma16816(acc[mt][nt], ah[mt], bh[nt]);
                    mma16816(acc[mt][nt], ah[mt], bl[nt]);
                    mma16816(acc[mt][nt], al[mt], bh[nt]);
                }
        }
        __syncthreads();
    }

#pragma unroll
    for (int mt = 0; mt < 2; mt++) {
        int r = bm + wm + mt * 16 + grp;
#pragma unroll
        for (int nt = 0; nt < 8; nt++) {
            int cc = bn + wn + nt * 8 + qd;
            *(float2*)&C[(size_t)r * N + cc]       = make_float2(acc[mt][nt][0], acc[mt][nt][1]);
            *(float2*)&C[(size_t)(r + 8) * N + cc] = make_float2(acc[mt][nt][2], acc[mt][nt][3]);
        }
    }
}

// ---------------------------------------------------------------------------
// RoPE in-place on fp32 K and V.
// ---------------------------------------------------------------------------
__global__ void rope_kernel(float* __restrict__ K, float* __restrict__ V,
                            const float* __restrict__ cosv,
                            const float* __restrict__ sinv) {
    int idx = blockIdx.x * blockDim.x + threadIdx.x;
    const int total = S_LEN * NKV * (HD / 2);
    if (idx >= total) return;

    int d2 = idx & 31;
    int h  = (idx >> 5) & (NKV - 1);
    int s  = idx >> 8;

    float c  = cosv[s * 32 + d2];
    float sn = sinv[s * 32 + d2];

    int base = s * KVD + h * HD + 2 * d2;

    float k0 = K[base], k1 = K[base + 1];
    K[base]     = k0 * c - k1 * sn;
    K[base + 1] = k0 * sn + k1 * c;

    float v0 = V[base], v1 = V[base + 1];
    V[base]     = v0 * c - v1 * sn;
    V[base + 1] = v0 * sn + v1 * c;
}

// ---------------------------------------------------------------------------
// MMA flash attention, causal GQA, split-bf16 x3 on both matmuls.
// Grid (S/128, NH), 256 threads (8 warps x 16 q-rows = 128 q-rows/block).
// KV chunks of 64. Writes Y directly as bf16 hi/lo.
// ---------------------------------------------------------------------------
#define AST 72   // smem stride (bf16 elems): frag loads hit 32 distinct banks

__global__ __launch_bounds__(256) void attn_mma(
    const __nv_bfloat16* __restrict__ Qhi, const __nv_bfloat16* __restrict__ Qlo,
    const __nv_bfloat16* __restrict__ Khi, const __nv_bfloat16* __restrict__ Klo,
    const __nv_bfloat16* __restrict__ VThi, const __nv_bfloat16* __restrict__ VTlo,
    __nv_bfloat16* __restrict__ Yhi, __nv_bfloat16* __restrict__ Ylo) {

    __shared__ __nv_bfloat16 sKh[64 * AST], sKl[64 * AST];
    __shared__ __nv_bfloat16 sVh[64 * AST], sVl[64 * AST];

    const int h    = blockIdx.y;
    const int kvh  = h >> 2;
    const int q0   = blockIdx.x * 128;
    const int tid  = threadIdx.x;
    const int lane = tid & 31;
    const int w    = tid >> 5;
    const int grp  = lane >> 2;
    const int qd   = (lane & 3) * 2;
    const int r0   = q0 + w * 16 + grp;       // this thread's first q row

    // Q fragments (A layout), loaded once from global
    uint32_t qh[4][4], ql[4][4];
#pragma unroll
    for (int jk = 0; jk < 4; jk++) {
        size_t c0 = (size_t)r0 * D_MODEL + h * HD + jk * 16 + qd;
        size_t c1 = (size_t)(r0 + 8) * D_MODEL + h * HD + jk * 16 + qd;
        qh[jk][0] = *(const uint32_t*)&Qhi[c0];
        qh[jk][1] = *(const uint32_t*)&Qhi[c1];
        qh[jk][2] = *(const uint32_t*)&Qhi[c0 + 8];
        qh[jk][3] = *(const uint32_t*)&Qhi[c1 + 8];
        ql[jk][0] = *(const uint32_t*)&Qlo[c0];
        ql[jk][1] = *(const uint32_t*)&Qlo[c1];
        ql[jk][2] = *(const uint32_t*)&Qlo[c0 + 8];
        ql[jk][3] = *(const uint32_t*)&Qlo[c1 + 8];
    }

    float o[8][4];
#pragma unroll
    for (int nt = 0; nt < 8; nt++)
#pragma unroll
        for (int i = 0; i < 4; i++) o[nt][i] = 0.f;

    float m0 = -1e30f, m1 = -1e30f, l0 = 0.f, l1 = 0.f;

    const int nChunks = (q0 >> 6) + 2;
    for (int ci = 0; ci < nChunks; ci++) {
        const int j0 = ci << 6;

        __syncthreads();   // previous chunk's smem reads complete
        // Stage K and Vt tiles (hi/lo): 64 rows x 128B each
#pragma unroll
        for (int i = 0; i < 2; i++) {
            int c   = tid + i * 256;       // 0..511
            int row = c >> 3;
            int cb  = (c & 7) * 16;
            uint32_t so = row * (AST * 2) + cb;
            const char* gk = (const char*)Khi + (size_t)(j0 + row) * (KVD * 2) + kvh * (HD * 2) + cb;
            *(uint4*)((char*)sKh + so) = *(const uint4*)gk;
            gk = (const char*)Klo + (size_t)(j0 + row) * (KVD * 2) + kvh * (HD * 2) + cb;
            *(uint4*)((char*)sKl + so) = *(const uint4*)gk;
            const char* gv = (const char*)VThi + (size_t)(kvh * HD + row) * (S_LEN * 2) + j0 * 2 + cb;
            *(uint4*)((char*)sVh + so) = *(const uint4*)gv;
            gv = (const char*)VTlo + (size_t)(kvh * HD + row) * (S_LEN * 2) + j0 * 2 + cb;
            *(uint4*)((char*)sVl + so) = *(const uint4*)gv;
        }
        __syncthreads();

        // S = Q K^T (x3)
        float s[8][4];
#pragma unroll
        for (int nt = 0; nt < 8; nt++)
#pragma unroll
            for (int i = 0; i < 4; i++) s[nt][i] = 0.f;

#pragma unroll
        for (int jk = 0; jk < 4; jk++) {
#pragma unroll
            for (int nt = 0; nt < 8; nt++) {
                const int ro = (nt * 8 + grp) * AST + jk * 16 + qd;
                uint32_t bh[2], bl[2];
                bh[0] = *(const uint32_t*)&sKh[ro];
                bh[1] = *(const uint32_t*)&sKh[ro + 8];
                bl[0] = *(const uint32_t*)&sKl[ro];
                bl[1] = *(const uint32_t*)&sKl[ro + 8];
                mma16816(s[nt], qh[jk], bh);
                mma16816(s[nt], qh[jk], bl);
                mma16816(s[nt], ql[jk], bh);
            }
        }

        // causal mask (only chunks overlapping the diagonal)
        if (ci >= nChunks - 2) {
#pragma unroll
            for (int nt = 0; nt < 8; nt++) {
                int col = j0 + nt * 8 + qd;
                if (col     > r0)     s[nt][0] = -1e30f;
                if (col + 1 > r0)     s[nt][1] = -1e30f;
                if (col     > r0 + 8) s[nt][2] = -1e30f;
                if (col + 1 > r0 + 8) s[nt][3] = -1e30f;
            }
        }

        // row max
        float mx0 = -1e30f, mx1 = -1e30f;
#pragma unroll
        for (int nt = 0; nt < 8; nt++) {
            mx0 = fmaxf(mx0, fmaxf(s[nt][0], s[nt][1]));
            mx1 = fmaxf(mx1, fmaxf(s[nt][2], s[nt][3]));
        }
        mx0 = fmaxf(mx0, __shfl_xor_sync(0xffffffffu, mx0, 1));
        mx0 = fmaxf(mx0, __shfl_xor_sync(0xffffffffu, mx0, 2));
        mx1 = fmaxf(mx1, __shfl_xor_sync(0xffffffffu, mx1, 1));
        mx1 = fmaxf(mx1, __shfl_xor_sync(0xffffffffu, mx1, 2));

        float nm0 = fmaxf(m0, mx0), nm1 = fmaxf(m1, mx1);
        float corr0 = __expf(m0 - nm0), corr1 = __expf(m1 - nm1);

        // P = exp(S - m), split to bf16 hi/lo, packed into A fragments
        uint32_t ph[4][4], pl[4][4];
        float sum0 = 0.f, sum1 = 0.f;
#pragma unroll
        for (int nt = 0; nt < 8; nt++) {
            float p0 = __expf(s[nt][0] - nm0), p1 = __expf(s[nt][1] - nm0);
            float p2 = __expf(s[nt][2] - nm1), p3 = __expf(s[nt][3] - nm1);
            sum0 += p0 + p1;
            sum1 += p2 + p3;
            uint32_t h01 = pack_bf16x2(p0, p1);
            uint32_t h23 = pack_bf16x2(p2, p3);
            float2 f01 = unpack_bf16x2(h01);
            float2 f23 = unpack_bf16x2(h23);
            uint32_t lo01 = pack_bf16x2(p0 - f01.x, p1 - f01.y);
            uint32_t lo23 = pack_bf16x2(p2 - f23.x, p3 - f23.y);
            int jk2 = nt >> 1, hf = (nt & 1) * 2;
            ph[jk2][hf]     = h01;
            ph[jk2][hf + 1] = h23;
            pl[jk2][hf]     = lo01;
            pl[jk2][hf + 1] = lo23;
        }
        sum0 += __shfl_xor_sync(0xffffffffu, sum0, 1);
        sum0 += __shfl_xor_sync(0xffffffffu, sum0, 2);
        sum1 += __shfl_xor_sync(0xffffffffu, sum1, 1);
        sum1 += __shfl_xor_sync(0xffffffffu, sum1, 2);
        l0 = l0 * corr0 + sum0;
        l1 = l1 * corr1 + sum1;
        m0 = nm0; m1 = nm1;

        // rescale O
#pragma unroll
        for (int nt = 0; nt < 8; nt++) {
            o[nt][0] *= corr0; o[nt][1] *= corr0;
            o[nt][2] *= corr1; o[nt][3] *= corr1;
        }

        // O += P V (x3)
#pragma unroll
        for (int jk = 0; jk < 4; jk++) {
#pragma unroll
            for (int nt = 0; nt < 8; nt++) {
                const int ro = (nt * 8 + grp) * AST + jk * 16 + qd;
                uint32_t bh[2], bl[2];
                bh[0] = *(const uint32_t*)&sVh[ro];
                bh[1] = *(const uint32_t*)&sVh[ro + 8];
                bl[0] = *(const uint32_t*)&sVl[ro];
                bl[1] = *(const uint32_t*)&sVl[ro + 8];
                mma16816(o[nt], ph[jk], bh);
                mma16816(o[nt], ph[jk], bl);
                mma16816(o[nt], pl[jk], bh);
            }
        }
    }

    // epilogue: normalize, split to bf16 hi/lo, store
    float il0 = 1.f / l0, il1 = 1.f / l1;
#pragma unroll
    for (int nt = 0; nt < 8; nt++) {
        float v0 = o[nt][0] * il0, v1 = o[nt][1] * il0;
        float v2 = o[nt][2] * il1, v3 = o[nt][3] * il1;
        uint32_t h01 = pack_bf16x2(v0, v1);
        uint32_t h23 = pack_bf16x2(v2, v3);
        float2 f01 = unpack_bf16x2(h01);
        float2 f23 = unpack_bf16x2(h23);
        uint32_t lo01 = pack_bf16x2(v0 - f01.x, v1 - f01.y);
        uint32_t lo23 = pack_bf16x2(v2 - f23.x, v3 - f23.y);
        size_t c0 = (size_t)r0 * D_MODEL + h * HD + nt * 8 + qd;
        size_t c1 = (size_t)(r0 + 8) * D_MODEL + h * HD + nt * 8 + qd;
        *(uint32_t*)&Yhi[c0] = h01;
        *(uint32_t*)&Yhi[c1] = h23;
        *(uint32_t*)&Ylo[c0] = lo01;
        *(uint32_t*)&Ylo[c1] = lo23;
    }
}

// ---------------------------------------------------------------------------
extern "C" void kernel_launch(void* const* d_in, const int* in_sizes, int n_in,
                              void* d_out, int out_size) {
    const float* x    = (const float*)d_in[0];
    const float* tcos = (const float*)d_in[1];
    const float* tsin = (const float*)d_in[2];
    const float* wq   = (const float*)d_in[3];
    const float* wk   = (const float*)d_in[4];
    const float* wv   = (const float*)d_in[5];
    const float* wo   = (const float*)d_in[6];
    float* out = (float*)d_out;

    float *Q, *K, *V;
    cudaGetSymbolAddress((void**)&Q, g_Q);
    cudaGetSymbolAddress((void**)&K, g_K);
    cudaGetSymbolAddress((void**)&V, g_V);

    __nv_bfloat16 *xhi, *xlo, *yhi, *ylo, *qhi, *qlo, *khi, *klo, *vthi, *vtlo;
    __nv_bfloat16 *wqThi, *wqTlo, *wkThi, *wkTlo, *wvThi, *wvTlo, *woThi, *woTlo;
    cudaGetSymbolAddress((void**)&xhi, g_xhi);   cudaGetSymbolAddress((void**)&xlo, g_xlo);
    cudaGetSymbolAddress((void**)&yhi, g_yhi);   cudaGetSymbolAddress((void**)&ylo, g_ylo);
    cudaGetSymbolAddress((void**)&qhi, g_qhi);   cudaGetSymbolAddress((void**)&qlo, g_qlo);
    cudaGetSymbolAddress((void**)&khi, g_khi);   cudaGetSymbolAddress((void**)&klo, g_klo);
    cudaGetSymbolAddress((void**)&vthi, g_vthi); cudaGetSymbolAddress((void**)&vtlo, g_vtlo);
    cudaGetSymbolAddress((void**)&wqThi, g_wqT_hi); cudaGetSymbolAddress((void**)&wqTlo, g_wqT_lo);
    cudaGetSymbolAddress((void**)&wkThi, g_wkT_hi); cudaGetSymbolAddress((void**)&wkTlo, g_wkT_lo);
    cudaGetSymbolAddress((void**)&wvThi, g_wvT_hi); cudaGetSymbolAddress((void**)&wvTlo, g_wvT_lo);
    cudaGetSymbolAddress((void**)&woThi, g_woT_hi); cudaGetSymbolAddress((void**)&woTlo, g_woT_lo);

    const int nx = S_LEN * D_MODEL;
    const int nkv = S_LEN * KVD;

    // Split x into bf16 hi/lo
    split_kernel<<<(nx + 255) / 256, 256>>>(x, xhi, xlo, nx, 1.0f);

    // Transpose+split weights: W[K][N] -> WT[N][K]
    transpose_split_kernel<<<dim3(D_MODEL / 32, D_MODEL / 32), dim3(32, 8)>>>(wq, wqThi, wqTlo, D_MODEL, D_MODEL);
    transpose_split_kernel<<<dim3(KVD / 32,     D_MODEL / 32), dim3(32, 8)>>>(wk, wkThi, wkTlo, D_MODEL, KVD);
    transpose_split_kernel<<<dim3(KVD / 32,     D_MODEL / 32), dim3(32, 8)>>>(wv, wvThi, wvTlo, D_MODEL, KVD);
    transpose_split_kernel<<<dim3(D_MODEL / 32, D_MODEL / 32), dim3(32, 8)>>>(wo, woThi, woTlo, D_MODEL, D_MODEL);

    // Projections (tensor cores)
    gemm_mma_x3<<<dim3(D_MODEL / 128, S_LEN / 128), 256>>>(xhi, xlo, wqThi, wqTlo, Q, D_MODEL, D_MODEL);
    gemm_mma_x3<<<dim3(KVD / 128,     S_LEN / 128), 256>>>(xhi, xlo, wkThi, wkTlo, K, KVD, D_MODEL);
    gemm_mma_x3<<<dim3(KVD / 128,     S_LEN / 128), 256>>>(xhi, xlo, wvThi, wvTlo, V, KVD, D_MODEL);

    // RoPE (fp32, in place)
    {
        int total = S_LEN * NKV * (HD / 2);
        rope_kernel<<<(total + 255) / 256, 256>>>(K, V, tcos, tsin);
    }

    // Prepare attention operands: Q scaled+split, K split, V transposed+split
    split_kernel<<<(nx + 255) / 256, 256>>>(Q, qhi, qlo, nx, 0.125f);
    split_kernel<<<(nkv + 255) / 256, 256>>>(K, khi, klo, nkv, 1.0f);
    transpose_split_kernel<<<dim3(KVD / 32, S_LEN / 32), dim3(32, 8)>>>(V, vthi, vtlo, S_LEN, KVD);

    // MMA flash attention -> Yhi/Ylo (bf16 split, ready for wo GEMM)
    attn_mma<<<dim3(S_LEN / 128, NH), 256>>>(qhi, qlo, khi, klo, vthi, vtlo, yhi, ylo);

    // Output projection
    gemm_mma_x3<<<dim3(D_MODEL / 128, S_LEN / 128), 256>>>(yhi, ylo, woThi, woTlo, out, D_MODEL, D_MODEL);
}

// round 7
// speedup vs baseline: 3.8632x; 1.1913x over previous
#include <cuda_runtime.h>
#include <cuda_bf16.h>
#include <stdint.h>
#include <math.h>

#define S_LEN   2048
#define D_MODEL 2048
#define HD      64
#define NH      32
#define NKV     8
#define KVD     (NKV * HD)   // 512

// ---------------------------------------------------------------------------
// Scratch (__device__ globals; no allocation allowed)
// ---------------------------------------------------------------------------
__device__ float g_V[S_LEN * KVD];

__device__ __nv_bfloat16 g_xhi[S_LEN * D_MODEL], g_xlo[S_LEN * D_MODEL];
__device__ __nv_bfloat16 g_yhi[S_LEN * D_MODEL], g_ylo[S_LEN * D_MODEL];
__device__ __nv_bfloat16 g_qhi[S_LEN * D_MODEL], g_qlo[S_LEN * D_MODEL];
__device__ __nv_bfloat16 g_khi[S_LEN * KVD],     g_klo[S_LEN * KVD];
__device__ __nv_bfloat16 g_vthi[KVD * S_LEN],    g_vtlo[KVD * S_LEN];
__device__ __nv_bfloat16 g_wqT_hi[D_MODEL * D_MODEL], g_wqT_lo[D_MODEL * D_MODEL];
__device__ __nv_bfloat16 g_woT_hi[D_MODEL * D_MODEL], g_woT_lo[D_MODEL * D_MODEL];
__device__ __nv_bfloat16 g_wkT_hi[KVD * D_MODEL],     g_wkT_lo[KVD * D_MODEL];
__device__ __nv_bfloat16 g_wvT_hi[KVD * D_MODEL],     g_wvT_lo[KVD * D_MODEL];

// ---------------------------------------------------------------------------
// PTX helpers
// ---------------------------------------------------------------------------
__device__ __forceinline__ uint32_t smem_u32(const void* p) {
    uint32_t a;
    asm("{ .reg .u64 t; cvta.to.shared.u64 t, %1; cvt.u32.u64 %0, t; }" : "=r"(a) : "l"(p));
    return a;
}
__device__ __forceinline__ void mma16816(float* c, const uint32_t* a, const uint32_t* b) {
    asm volatile(
        "mma.sync.aligned.m16n8k16.row.col.f32.bf16.bf16.f32 "
        "{%0,%1,%2,%3}, {%4,%5,%6,%7}, {%8,%9}, {%0,%1,%2,%3};"
        : "+f"(c[0]), "+f"(c[1]), "+f"(c[2]), "+f"(c[3])
        : "r"(a[0]), "r"(a[1]), "r"(a[2]), "r"(a[3]), "r"(b[0]), "r"(b[1]));
}
#define CP_ASYNC16(dst, src) \
    asm volatile("cp.async.cg.shared.global [%0], [%1], 16;" :: "r"(dst), "l"(src))
#define CP_COMMIT() asm volatile("cp.async.commit_group;" ::: "memory")
#define CP_WAIT1()  asm volatile("cp.async.wait_group 1;" ::: "memory")
#define CP_WAIT0()  asm volatile("cp.async.wait_group 0;" ::: "memory")

__device__ __forceinline__ uint32_t pack_bf16x2(float lo, float hi) {
    __nv_bfloat162 t = __floats2bfloat162_rn(lo, hi);
    return *reinterpret_cast<uint32_t*>(&t);
}
__device__ __forceinline__ float2 unpack_bf16x2(uint32_t u) {
    __nv_bfloat162 t = *reinterpret_cast<__nv_bfloat162*>(&u);
    return make_float2(__bfloat162float(t.x), __bfloat162float(t.y));
}
__device__ __forceinline__ void store_split(__nv_bfloat16* Hi, __nv_bfloat16* Lo,
                                            size_t idx, float v0, float v1) {
    uint32_t h = pack_bf16x2(v0, v1);
    float2 f = unpack_bf16x2(h);
    uint32_t l = pack_bf16x2(v0 - f.x, v1 - f.y);
    *(uint32_t*)&Hi[idx] = h;
    *(uint32_t*)&Lo[idx] = l;
}

// ---------------------------------------------------------------------------
// Split fp32 -> bf16 hi + lo
// ---------------------------------------------------------------------------
__global__ void split_kernel(const float* __restrict__ src,
                             __nv_bfloat16* __restrict__ hi,
                             __nv_bfloat16* __restrict__ lo, int n, float scale) {
    int i = blockIdx.x * 256 + threadIdx.x;
    if (i >= n) return;
    float v = src[i] * scale;
    __nv_bfloat16 h = __float2bfloat16(v);
    hi[i] = h;
    lo[i] = __float2bfloat16(v - __bfloat162float(h));
}

// ---------------------------------------------------------------------------
// Transpose + split: W[rows][Nd] fp32 -> WT[Nd][rows] bf16 hi/lo
// ---------------------------------------------------------------------------
__global__ void transpose_split_kernel(const float* __restrict__ W,
                                       __nv_bfloat16* __restrict__ Thi,
                                       __nv_bfloat16* __restrict__ Tlo,
                                       int Kd, int Nd) {
    __shared__ float t[32][33];
    int bx = blockIdx.x * 32;
    int by = blockIdx.y * 32;
    int tx = threadIdx.x, ty = threadIdx.y;
#pragma unroll
    for (int j = 0; j < 32; j += 8)
        t[ty + j][tx] = W[(size_t)(by + ty + j) * Nd + bx + tx];
    __syncthreads();
#pragma unroll
    for (int j = 0; j < 32; j += 8) {
        int n = bx + ty + j, k = by + tx;
        float v = t[tx][ty + j];
        __nv_bfloat16 h = __float2bfloat16(v);
        Thi[(size_t)n * Kd + k] = h;
        Tlo[(size_t)n * Kd + k] = __float2bfloat16(v - __bfloat162float(h));
    }
}

// ---------------------------------------------------------------------------
// Pipelined warp-MMA GEMM, split-bf16 x3: C = (Ahi+Alo)[M,K]*(Bhi+Blo)[N,K]^T
// 2-stage cp.async double buffering. Epilogue modes:
//   0: fp32 C      1: scale + bf16 hi/lo      2: RoPE + bf16 hi/lo
//   3: RoPE + fp32
// ---------------------------------------------------------------------------
#define SA  40
#define GTB (128 * SA * 2)          // bytes per tile buffer (10240)
#define GEMM_SMEM (2 * 4 * GTB)     // 81920

__global__ __launch_bounds__(256) void gemm_mma_x3(
    const __nv_bfloat16* __restrict__ Ahi, const __nv_bfloat16* __restrict__ Alo,
    const __nv_bfloat16* __restrict__ Bhi, const __nv_bfloat16* __restrict__ Blo,
    float* __restrict__ Cf, __nv_bfloat16* __restrict__ Chi, __nv_bfloat16* __restrict__ Clo,
    const float* __restrict__ cosv, const float* __restrict__ sinv,
    int N, int Kd, int mode, float scale) {

    extern __shared__ char dsm[];
    uint32_t sb = smem_u32(dsm);

    const int tid  = threadIdx.x;
    const int lane = tid & 31;
    const int wid  = tid >> 5;
    const int wm   = (wid >> 1) * 32;
    const int wn   = (wid & 1) * 64;
    const int bm   = blockIdx.y * 128;
    const int bn   = blockIdx.x * 128;
    const int lrow = tid >> 2;
    const int lcb  = (tid & 3) * 16;
    const int grp  = lane >> 2;
    const int qd   = (lane & 3) * 2;

    const int nIter = Kd / 32;

    auto issue = [&](int it, int stage) {
        const size_t kb = (size_t)it * 64;
        uint32_t base = sb + stage * (4 * GTB);
#pragma unroll
        for (int rr = 0; rr < 2; rr++) {
            int row = lrow + rr * 64;
            uint32_t so = row * (SA * 2) + lcb;
            const char* g = (const char*)Ahi + ((size_t)(bm + row) * Kd) * 2 + kb + lcb;
            CP_ASYNC16(base + so, g);
            g = (const char*)Alo + ((size_t)(bm + row) * Kd) * 2 + kb + lcb;
            CP_ASYNC16(base + GTB + so, g);
            g = (const char*)Bhi + ((size_t)(bn + row) * Kd) * 2 + kb + lcb;
            CP_ASYNC16(base + 2 * GTB + so, g);
            g = (const char*)Blo + ((size_t)(bn + row) * Kd) * 2 + kb + lcb;
            CP_ASYNC16(base + 3 * GTB + so, g);
        }
        CP_COMMIT();
    };

    float acc[2][8][4];
#pragma unroll
    for (int i = 0; i < 2; i++)
#pragma unroll
        for (int j = 0; j < 8; j++)
#pragma unroll
            for (int k = 0; k < 4; k++) acc[i][j][k] = 0.f;

    issue(0, 0);
    if (nIter > 1) issue(1, 1);

    for (int it = 0; it < nIter; it++) {
        if (it + 1 < nIter) { CP_WAIT1(); } else { CP_WAIT0(); }
        __syncthreads();

        const __nv_bfloat16* sAh = (const __nv_bfloat16*)(dsm + (it & 1) * (4 * GTB));
        const __nv_bfloat16* sAl = sAh + 128 * SA;
        const __nv_bfloat16* sBh = sAl + 128 * SA;
        const __nv_bfloat16* sBl = sBh + 128 * SA;

#pragma unroll
        for (int ks = 0; ks < 2; ks++) {
            const int kc = ks * 16;
            uint32_t ah[2][4], al[2][4];
#pragma unroll
            for (int mt = 0; mt < 2; mt++) {
                int r = wm + mt * 16 + grp;
                int c = kc + qd;
                ah[mt][0] = *(const uint32_t*)&sAh[r * SA + c];
                ah[mt][1] = *(const uint32_t*)&sAh[(r + 8) * SA + c];
                ah[mt][2] = *(const uint32_t*)&sAh[r * SA + c + 8];
                ah[mt][3] = *(const uint32_t*)&sAh[(r + 8) * SA + c + 8];
                al[mt][0] = *(const uint32_t*)&sAl[r * SA + c];
                al[mt][1] = *(const uint32_t*)&sAl[(r + 8) * SA + c];
                al[mt][2] = *(const uint32_t*)&sAl[r * SA + c + 8];
                al[mt][3] = *(const uint32_t*)&sAl[(r + 8) * SA + c + 8];
            }
            uint32_t bh[8][2], bl[8][2];
#pragma unroll
            for (int nt = 0; nt < 8; nt++) {
                int n = wn + nt * 8 + grp;
                int c = kc + qd;
                bh[nt][0] = *(const uint32_t*)&sBh[n * SA + c];
                bh[nt][1] = *(const uint32_t*)&sBh[n * SA + c + 8];
                bl[nt][0] = *(const uint32_t*)&sBl[n * SA + c];
                bl[nt][1] = *(const uint32_t*)&sBl[n * SA + c + 8];
            }
#pragma unroll
            for (int mt = 0; mt < 2; mt++)
#pragma unroll
                for (int nt = 0; nt < 8; nt++) {
                    mma16816(acc[mt][nt], ah[mt], bh[nt]);
                    mma16816(acc[mt][nt], ah[mt], bl[nt]);
                    mma16816(acc[mt][nt], al[mt], bh[nt]);
                }
        }
        __syncthreads();
        if (it + 2 < nIter) issue(it + 2, it & 1);
    }

    // ---- epilogue ----
#pragma unroll
    for (int mt = 0; mt < 2; mt++) {
        int r = bm + wm + mt * 16 + grp;
#pragma unroll
        for (int nt = 0; nt < 8; nt++) {
            int c = bn + wn + nt * 8 + qd;
            float a0 = acc[mt][nt][0], a1 = acc[mt][nt][1];
            float a2 = acc[mt][nt][2], a3 = acc[mt][nt][3];
            size_t i0 = (size_t)r * N + c;
            size_t i1 = (size_t)(r + 8) * N + c;
            if (mode == 0) {
                *(float2*)&Cf[i0] = make_float2(a0, a1);
                *(float2*)&Cf[i1] = make_float2(a2, a3);
            } else if (mode == 1) {
                store_split(Chi, Clo, i0, a0 * scale, a1 * scale);
                store_split(Chi, Clo, i1, a2 * scale, a3 * scale);
            } else {
                int d2 = (c & 63) >> 1;
                float c0 = cosv[r * 32 + d2],       s0 = sinv[r * 32 + d2];
                float c1 = cosv[(r + 8) * 32 + d2], s1 = sinv[(r + 8) * 32 + d2];
                float o0 = a0 * c0 - a1 * s0, o1 = a0 * s0 + a1 * c0;
                float o2 = a2 * c1 - a3 * s1, o3 = a2 * s1 + a3 * c1;
                if (mode == 3) {
                    *(float2*)&Cf[i0] = make_float2(o0, o1);
                    *(float2*)&Cf[i1] = make_float2(o2, o3);
                } else {
                    store_split(Chi, Clo, i0, o0, o1);
                    store_split(Chi, Clo, i1, o2, o3);
                }
            }
        }
    }
}

// ---------------------------------------------------------------------------
// Pipelined MMA flash attention, causal GQA, split-bf16 x3 on both matmuls.
// Grid (S/128, NH), 256 threads. 2-stage cp.async KV staging.
// ---------------------------------------------------------------------------
#define AST 72
#define ATB (64 * AST * 2)          // 9216
#define ATTN_SMEM (2 * 4 * ATB)     // 73728

__global__ __launch_bounds__(256) void attn_mma(
    const __nv_bfloat16* __restrict__ Qhi, const __nv_bfloat16* __restrict__ Qlo,
    const __nv_bfloat16* __restrict__ Khi, const __nv_bfloat16* __restrict__ Klo,
    const __nv_bfloat16* __restrict__ VThi, const __nv_bfloat16* __restrict__ VTlo,
    __nv_bfloat16* __restrict__ Yhi, __nv_bfloat16* __restrict__ Ylo) {

    extern __shared__ char dsm[];
    uint32_t sb = smem_u32(dsm);

    const int h    = blockIdx.y;
    const int kvh  = h >> 2;
    const int q0   = blockIdx.x * 128;
    const int tid  = threadIdx.x;
    const int lane = tid & 31;
    const int w    = tid >> 5;
    const int grp  = lane >> 2;
    const int qd   = (lane & 3) * 2;
    const int r0   = q0 + w * 16 + grp;

    const int nChunks = (q0 >> 6) + 2;

    auto issueA = [&](int ci, int stage) {
        const int j0 = ci << 6;
        uint32_t base = sb + stage * (4 * ATB);
#pragma unroll
        for (int i = 0; i < 2; i++) {
            int c   = tid + i * 256;
            int row = c >> 3;
            int cb  = (c & 7) * 16;
            uint32_t so = row * (AST * 2) + cb;
            const char* g = (const char*)Khi + ((size_t)(j0 + row) * KVD + kvh * HD) * 2 + cb;
            CP_ASYNC16(base + so, g);
            g = (const char*)Klo + ((size_t)(j0 + row) * KVD + kvh * HD) * 2 + cb;
            CP_ASYNC16(base + ATB + so, g);
            g = (const char*)VThi + ((size_t)(kvh * HD + row) * S_LEN + j0) * 2 + cb;
            CP_ASYNC16(base + 2 * ATB + so, g);
            g = (const char*)VTlo + ((size_t)(kvh * HD + row) * S_LEN + j0) * 2 + cb;
            CP_ASYNC16(base + 3 * ATB + so, g);
        }
        CP_COMMIT();
    };

    // Q fragments, loaded once
    uint32_t qh[4][4], ql[4][4];
#pragma unroll
    for (int jk = 0; jk < 4; jk++) {
        size_t c0 = (size_t)r0 * D_MODEL + h * HD + jk * 16 + qd;
        size_t c1 = (size_t)(r0 + 8) * D_MODEL + h * HD + jk * 16 + qd;
        qh[jk][0] = *(const uint32_t*)&Qhi[c0];
        qh[jk][1] = *(const uint32_t*)&Qhi[c1];
        qh[jk][2] = *(const uint32_t*)&Qhi[c0 + 8];
        qh[jk][3] = *(const uint32_t*)&Qhi[c1 + 8];
        ql[jk][0] = *(const uint32_t*)&Qlo[c0];
        ql[jk][1] = *(const uint32_t*)&Qlo[c1];
        ql[jk][2] = *(const uint32_t*)&Qlo[c0 + 8];
        ql[jk][3] = *(const uint32_t*)&Qlo[c1 + 8];
    }

    float o[8][4];
#pragma unroll
    for (int nt = 0; nt < 8; nt++)
#pragma unroll
        for (int i = 0; i < 4; i++) o[nt][i] = 0.f;

    float m0 = -1e30f, m1 = -1e30f, l0 = 0.f, l1 = 0.f;

    issueA(0, 0);
    if (nChunks > 1) issueA(1, 1);

    for (int ci = 0; ci < nChunks; ci++) {
        const int j0 = ci << 6;
        if (ci + 1 < nChunks) { CP_WAIT1(); } else { CP_WAIT0(); }
        __syncthreads();

        const __nv_bfloat16* sKh = (const __nv_bfloat16*)(dsm + (ci & 1) * (4 * ATB));
        const __nv_bfloat16* sKl = sKh + 64 * AST;
        const __nv_bfloat16* sVh = sKl + 64 * AST;
        const __nv_bfloat16* sVl = sVh + 64 * AST;

        // S = Q K^T (x3)
        float s[8][4];
#pragma unroll
        for (int nt = 0; nt < 8; nt++)
#pragma unroll
            for (int i = 0; i < 4; i++) s[nt][i] = 0.f;

#pragma unroll
        for (int jk = 0; jk < 4; jk++) {
#pragma unroll
            for (int nt = 0; nt < 8; nt++) {
                const int ro = (nt * 8 + grp) * AST + jk * 16 + qd;
                uint32_t bh[2], bl[2];
                bh[0] = *(const uint32_t*)&sKh[ro];
                bh[1] = *(const uint32_t*)&sKh[ro + 8];
                bl[0] = *(const uint32_t*)&sKl[ro];
                bl[1] = *(const uint32_t*)&sKl[ro + 8];
                mma16816(s[nt], qh[jk], bh);
                mma16816(s[nt], qh[jk], bl);
                mma16816(s[nt], ql[jk], bh);
            }
        }

        if (ci >= nChunks - 2) {
#pragma unroll
            for (int nt = 0; nt < 8; nt++) {
                int col = j0 + nt * 8 + qd;
                if (col     > r0)     s[nt][0] = -1e30f;
                if (col + 1 > r0)     s[nt][1] = -1e30f;
                if (col     > r0 + 8) s[nt][2] = -1e30f;
                if (col + 1 > r0 + 8) s[nt][3] = -1e30f;
            }
        }

        float mx0 = -1e30f, mx1 = -1e30f;
#pragma unroll
        for (int nt = 0; nt < 8; nt++) {
            mx0 = fmaxf(mx0, fmaxf(s[nt][0], s[nt][1]));
            mx1 = fmaxf(mx1, fmaxf(s[nt][2], s[nt][3]));
        }
        mx0 = fmaxf(mx0, __shfl_xor_sync(0xffffffffu, mx0, 1));
        mx0 = fmaxf(mx0, __shfl_xor_sync(0xffffffffu, mx0, 2));
        mx1 = fmaxf(mx1, __shfl_xor_sync(0xffffffffu, mx1, 1));
        mx1 = fmaxf(mx1, __shfl_xor_sync(0xffffffffu, mx1, 2));

        float nm0 = fmaxf(m0, mx0), nm1 = fmaxf(m1, mx1);
        float corr0 = __expf(m0 - nm0), corr1 = __expf(m1 - nm1);

        uint32_t ph[4][4], pl[4][4];
        float sum0 = 0.f, sum1 = 0.f;
#pragma unroll
        for (int nt = 0; nt < 8; nt++) {
            float p0 = __expf(s[nt][0] - nm0), p1 = __expf(s[nt][1] - nm0);
            float p2 = __expf(s[nt][2] - nm1), p3 = __expf(s[nt][3] - nm1);
            sum0 += p0 + p1;
            sum1 += p2 + p3;
            uint32_t h01 = pack_bf16x2(p0, p1);
            uint32_t h23 = pack_bf16x2(p2, p3);
            float2 f01 = unpack_bf16x2(h01);
            float2 f23 = unpack_bf16x2(h23);
            uint32_t lo01 = pack_bf16x2(p0 - f01.x, p1 - f01.y);
            uint32_t lo23 = pack_bf16x2(p2 - f23.x, p3 - f23.y);
            int jk2 = nt >> 1, hf = (nt & 1) * 2;
            ph[jk2][hf]     = h01;
            ph[jk2][hf + 1] = h23;
            pl[jk2][hf]     = lo01;
            pl[jk2][hf + 1] = lo23;
        }
        sum0 += __shfl_xor_sync(0xffffffffu, sum0, 1);
        sum0 += __shfl_xor_sync(0xffffffffu, sum0, 2);
        sum1 += __shfl_xor_sync(0xffffffffu, sum1, 1);
        sum1 += __shfl_xor_sync(0xffffffffu, sum1, 2);
        l0 = l0 * corr0 + sum0;
        l1 = l1 * corr1 + sum1;
        m0 = nm0; m1 = nm1;

#pragma unroll
        for (int nt = 0; nt < 8; nt++) {
            o[nt][0] *= corr0; o[nt][1] *= corr0;
            o[nt][2] *= corr1; o[nt][3] *= corr1;
        }

        // O += P V (x3)
#pragma unroll
        for (int jk = 0; jk < 4; jk++) {
#pragma unroll
            for (int nt = 0; nt < 8; nt++) {
                const int ro = (nt * 8 + grp) * AST + jk * 16 + qd;
                uint32_t bh[2], bl[2];
                bh[0] = *(const uint32_t*)&sVh[ro];
                bh[1] = *(const uint32_t*)&sVh[ro + 8];
                bl[0] = *(const uint32_t*)&sVl[ro];
                bl[1] = *(const uint32_t*)&sVl[ro + 8];
                mma16816(o[nt], ph[jk], bh);
                mma16816(o[nt], ph[jk], bl);
                mma16816(o[nt], pl[jk], bh);
            }
        }

        __syncthreads();
        if (ci + 2 < nChunks) issueA(ci + 2, ci & 1);
    }

    float il0 = 1.f / l0, il1 = 1.f / l1;
#pragma unroll
    for (int nt = 0; nt < 8; nt++) {
        size_t c0 = (size_t)r0 * D_MODEL + h * HD + nt * 8 + qd;
        size_t c1 = (size_t)(r0 + 8) * D_MODEL + h * HD + nt * 8 + qd;
        store_split(Yhi, Ylo, c0, o[nt][0] * il0, o[nt][1] * il0);
        store_split(Yhi, Ylo, c1, o[nt][2] * il1, o[nt][3] * il1);
    }
}

// ---------------------------------------------------------------------------
extern "C" void kernel_launch(void* const* d_in, const int* in_sizes, int n_in,
                              void* d_out, int out_size) {
    const float* x    = (const float*)d_in[0];
    const float* tcos = (const float*)d_in[1];
    const float* tsin = (const float*)d_in[2];
    const float* wq   = (const float*)d_in[3];
    const float* wk   = (const float*)d_in[4];
    const float* wv   = (const float*)d_in[5];
    const float* wo   = (const float*)d_in[6];
    float* out = (float*)d_out;

    float* V;
    cudaGetSymbolAddress((void**)&V, g_V);

    __nv_bfloat16 *xhi, *xlo, *yhi, *ylo, *qhi, *qlo, *khi, *klo, *vthi, *vtlo;
    __nv_bfloat16 *wqThi, *wqTlo, *wkThi, *wkTlo, *wvThi, *wvTlo, *woThi, *woTlo;
    cudaGetSymbolAddress((void**)&xhi, g_xhi);   cudaGetSymbolAddress((void**)&xlo, g_xlo);
    cudaGetSymbolAddress((void**)&yhi, g_yhi);   cudaGetSymbolAddress((void**)&ylo, g_ylo);
    cudaGetSymbolAddress((void**)&qhi, g_qhi);   cudaGetSymbolAddress((void**)&qlo, g_qlo);
    cudaGetSymbolAddress((void**)&khi, g_khi);   cudaGetSymbolAddress((void**)&klo, g_klo);
    cudaGetSymbolAddress((void**)&vthi, g_vthi); cudaGetSymbolAddress((void**)&vtlo, g_vtlo);
    cudaGetSymbolAddress((void**)&wqThi, g_wqT_hi); cudaGetSymbolAddress((void**)&wqTlo, g_wqT_lo);
    cudaGetSymbolAddress((void**)&wkThi, g_wkT_hi); cudaGetSymbolAddress((void**)&wkTlo, g_wkT_lo);
    cudaGetSymbolAddress((void**)&wvThi, g_wvT_hi); cudaGetSymbolAddress((void**)&wvTlo, g_wvT_lo);
    cudaGetSymbolAddress((void**)&woThi, g_woT_hi); cudaGetSymbolAddress((void**)&woTlo, g_woT_lo);

    cudaFuncSetAttribute(gemm_mma_x3, cudaFuncAttributeMaxDynamicSharedMemorySize, GEMM_SMEM);
    cudaFuncSetAttribute(attn_mma,    cudaFuncAttributeMaxDynamicSharedMemorySize, ATTN_SMEM);

    const int nx = S_LEN * D_MODEL;

    // Split x into bf16 hi/lo
    split_kernel<<<(nx + 255) / 256, 256>>>(x, xhi, xlo, nx, 1.0f);

    // Transpose+split weights: W[K][N] -> WT[N][K]
    transpose_split_kernel<<<dim3(D_MODEL / 32, D_MODEL / 32), dim3(32, 8)>>>(wq, wqThi, wqTlo, D_MODEL, D_MODEL);
    transpose_split_kernel<<<dim3(KVD / 32,     D_MODEL / 32), dim3(32, 8)>>>(wk, wkThi, wkTlo, D_MODEL, KVD);
    transpose_split_kernel<<<dim3(KVD / 32,     D_MODEL / 32), dim3(32, 8)>>>(wv, wvThi, wvTlo, D_MODEL, KVD);
    transpose_split_kernel<<<dim3(D_MODEL / 32, D_MODEL / 32), dim3(32, 8)>>>(wo, woThi, woTlo, D_MODEL, D_MODEL);

    // Q projection: fused scale + bf16 split epilogue
    gemm_mma_x3<<<dim3(D_MODEL / 128, S_LEN / 128), 256, GEMM_SMEM>>>(
        xhi, xlo, wqThi, wqTlo, nullptr, qhi, qlo, nullptr, nullptr,
        D_MODEL, D_MODEL, 1, 0.125f);
    // K projection: fused RoPE + bf16 split epilogue
    gemm_mma_x3<<<dim3(KVD / 128, S_LEN / 128), 256, GEMM_SMEM>>>(
        xhi, xlo, wkThi, wkTlo, nullptr, khi, klo, tcos, tsin,
        KVD, D_MODEL, 2, 1.0f);
    // V projection: fused RoPE, fp32 out (then transposed)
    gemm_mma_x3<<<dim3(KVD / 128, S_LEN / 128), 256, GEMM_SMEM>>>(
        xhi, xlo, wvThi, wvTlo, V, nullptr, nullptr, tcos, tsin,
        KVD, D_MODEL, 3, 1.0f);

    // V transpose+split for attention ([dim][seq])
    transpose_split_kernel<<<dim3(KVD / 32, S_LEN / 32), dim3(32, 8)>>>(V, vthi, vtlo, S_LEN, KVD);

    // MMA flash attention -> Yhi/Ylo
    attn_mma<<<dim3(S_LEN / 128, NH), 256, ATTN_SMEM>>>(qhi, qlo, khi, klo, vthi, vtlo, yhi, ylo);

    // Output projection (fp32 out)
    gemm_mma_x3<<<dim3(D_MODEL / 128, S_LEN / 128), 256, GEMM_SMEM>>>(
        yhi, ylo, woThi, woTlo, out, nullptr, nullptr, nullptr, nullptr,
        D_MODEL, D_MODEL, 0, 1.0f);
}

// round 8
// speedup vs baseline: 3.8664x; 1.0008x over previous
#include <cuda_runtime.h>
#include <cuda_bf16.h>
#include <stdint.h>
#include <math.h>

#define S_LEN   2048
#define D_MODEL 2048
#define HD      64
#define NH      32
#define NKV     8
#define KVD     (NKV * HD)   // 512

// ---------------------------------------------------------------------------
// Scratch (__device__ globals; no allocation allowed)
// ---------------------------------------------------------------------------
__device__ float g_V[S_LEN * KVD];

__device__ __nv_bfloat16 g_xhi[S_LEN * D_MODEL], g_xlo[S_LEN * D_MODEL];
__device__ __nv_bfloat16 g_yhi[S_LEN * D_MODEL], g_ylo[S_LEN * D_MODEL];
__device__ __nv_bfloat16 g_qhi[S_LEN * D_MODEL], g_qlo[S_LEN * D_MODEL];
__device__ __nv_bfloat16 g_khi[S_LEN * KVD],     g_klo[S_LEN * KVD];
__device__ __nv_bfloat16 g_vthi[KVD * S_LEN],    g_vtlo[KVD * S_LEN];
__device__ __nv_bfloat16 g_wqT_hi[D_MODEL * D_MODEL], g_wqT_lo[D_MODEL * D_MODEL];
__device__ __nv_bfloat16 g_woT_hi[D_MODEL * D_MODEL], g_woT_lo[D_MODEL * D_MODEL];
__device__ __nv_bfloat16 g_wkT_hi[KVD * D_MODEL],     g_wkT_lo[KVD * D_MODEL];
__device__ __nv_bfloat16 g_wvT_hi[KVD * D_MODEL],     g_wvT_lo[KVD * D_MODEL];

// ---------------------------------------------------------------------------
// PTX helpers
// ---------------------------------------------------------------------------
__device__ __forceinline__ uint32_t smem_u32(const void* p) {
    uint32_t a;
    asm("{ .reg .u64 t; cvta.to.shared.u64 t, %1; cvt.u32.u64 %0, t; }" : "=r"(a) : "l"(p));
    return a;
}
__device__ __forceinline__ void mma16816(float* c, const uint32_t* a, const uint32_t* b) {
    asm volatile(
        "mma.sync.aligned.m16n8k16.row.col.f32.bf16.bf16.f32 "
        "{%0,%1,%2,%3}, {%4,%5,%6,%7}, {%8,%9}, {%0,%1,%2,%3};"
        : "+f"(c[0]), "+f"(c[1]), "+f"(c[2]), "+f"(c[3])
        : "r"(a[0]), "r"(a[1]), "r"(a[2]), "r"(a[3]), "r"(b[0]), "r"(b[1]));
}
__device__ __forceinline__ void ldsm_x4(uint32_t* r, uint32_t addr) {
    asm volatile("ldmatrix.sync.aligned.m8n8.x4.shared.b16 {%0,%1,%2,%3}, [%4];"
        : "=r"(r[0]), "=r"(r[1]), "=r"(r[2]), "=r"(r[3]) : "r"(addr));
}
#define CP_ASYNC16(dst, src) \
    asm volatile("cp.async.cg.shared.global [%0], [%1], 16;" :: "r"(dst), "l"(src))
#define CP_COMMIT() asm volatile("cp.async.commit_group;" ::: "memory")
#define CP_WAIT1()  asm volatile("cp.async.wait_group 1;" ::: "memory")
#define CP_WAIT0()  asm volatile("cp.async.wait_group 0;" ::: "memory")

__device__ __forceinline__ uint32_t pack_bf16x2(float lo, float hi) {
    __nv_bfloat162 t = __floats2bfloat162_rn(lo, hi);
    return *reinterpret_cast<uint32_t*>(&t);
}
__device__ __forceinline__ float2 unpack_bf16x2(uint32_t u) {
    __nv_bfloat162 t = *reinterpret_cast<__nv_bfloat162*>(&u);
    return make_float2(__bfloat162float(t.x), __bfloat162float(t.y));
}
__device__ __forceinline__ void store_split(__nv_bfloat16* Hi, __nv_bfloat16* Lo,
                                            size_t idx, float v0, float v1) {
    uint32_t h = pack_bf16x2(v0, v1);
    float2 f = unpack_bf16x2(h);
    uint32_t l = pack_bf16x2(v0 - f.x, v1 - f.y);
    *(uint32_t*)&Hi[idx] = h;
    *(uint32_t*)&Lo[idx] = l;
}

// ---------------------------------------------------------------------------
// Split fp32 -> bf16 hi + lo
// ---------------------------------------------------------------------------
__global__ void split_kernel(const float* __restrict__ src,
                             __nv_bfloat16* __restrict__ hi,
                             __nv_bfloat16* __restrict__ lo, int n, float scale) {
    int i = blockIdx.x * 256 + threadIdx.x;
    if (i >= n) return;
    float v = src[i] * scale;
    __nv_bfloat16 h = __float2bfloat16(v);
    hi[i] = h;
    lo[i] = __float2bfloat16(v - __bfloat162float(h));
}

// ---------------------------------------------------------------------------
// Transpose + split: W[rows][Nd] fp32 -> WT[Nd][rows] bf16 hi/lo
// ---------------------------------------------------------------------------
__global__ void transpose_split_kernel(const float* __restrict__ W,
                                       __nv_bfloat16* __restrict__ Thi,
                                       __nv_bfloat16* __restrict__ Tlo,
                                       int Kd, int Nd) {
    __shared__ float t[32][33];
    int bx = blockIdx.x * 32;
    int by = blockIdx.y * 32;
    int tx = threadIdx.x, ty = threadIdx.y;
#pragma unroll
    for (int j = 0; j < 32; j += 8)
        t[ty + j][tx] = W[(size_t)(by + ty + j) * Nd + bx + tx];
    __syncthreads();
#pragma unroll
    for (int j = 0; j < 32; j += 8) {
        int n = bx + ty + j, k = by + tx;
        float v = t[tx][ty + j];
        __nv_bfloat16 h = __float2bfloat16(v);
        Thi[(size_t)n * Kd + k] = h;
        Tlo[(size_t)n * Kd + k] = __float2bfloat16(v - __bfloat162float(h));
    }
}

// ---------------------------------------------------------------------------
// Pipelined warp-MMA GEMM (ldmatrix), split-bf16 x3.
// Modes: 0 fp32 | 1 scale+bf16split | 2 RoPE+bf16split | 3 RoPE+fp32
// ---------------------------------------------------------------------------
#define SA  40
#define GTB (128 * SA * 2)          // 10240
#define GEMM_SMEM (2 * 4 * GTB)     // 81920

__global__ __launch_bounds__(256) void gemm_mma_x3(
    const __nv_bfloat16* __restrict__ Ahi, const __nv_bfloat16* __restrict__ Alo,
    const __nv_bfloat16* __restrict__ Bhi, const __nv_bfloat16* __restrict__ Blo,
    float* __restrict__ Cf, __nv_bfloat16* __restrict__ Chi, __nv_bfloat16* __restrict__ Clo,
    const float* __restrict__ cosv, const float* __restrict__ sinv,
    int N, int Kd, int mode, float scale) {

    extern __shared__ char dsm[];
    uint32_t sb = smem_u32(dsm);

    const int tid  = threadIdx.x;
    const int lane = tid & 31;
    const int wid  = tid >> 5;
    const int wm   = (wid >> 1) * 32;
    const int wn   = (wid & 1) * 64;
    const int bm   = blockIdx.y * 128;
    const int bn   = blockIdx.x * 128;
    const int lrow = tid >> 2;
    const int lcb  = (tid & 3) * 16;
    const int grp  = lane >> 2;
    const int qd   = (lane & 3) * 2;

    // ldmatrix lane->row/col mappings
    const int arow_l = (lane & 7) + (((lane >> 3) & 1) << 3);
    const int acol_l = (lane >> 4) << 3;
    const int brow_l = (lane & 7) + ((lane >> 4) << 3);
    const int bcol_l = ((lane >> 3) & 1) << 3;

    const int nIter = Kd / 32;

    auto issue = [&](int it, int stage) {
        const size_t kb = (size_t)it * 64;
        uint32_t base = sb + stage * (4 * GTB);
#pragma unroll
        for (int rr = 0; rr < 2; rr++) {
            int row = lrow + rr * 64;
            uint32_t so = row * (SA * 2) + lcb;
            const char* g = (const char*)Ahi + ((size_t)(bm + row) * Kd) * 2 + kb + lcb;
            CP_ASYNC16(base + so, g);
            g = (const char*)Alo + ((size_t)(bm + row) * Kd) * 2 + kb + lcb;
            CP_ASYNC16(base + GTB + so, g);
            g = (const char*)Bhi + ((size_t)(bn + row) * Kd) * 2 + kb + lcb;
            CP_ASYNC16(base + 2 * GTB + so, g);
            g = (const char*)Blo + ((size_t)(bn + row) * Kd) * 2 + kb + lcb;
            CP_ASYNC16(base + 3 * GTB + so, g);
        }
        CP_COMMIT();
    };

    float acc[2][8][4];
#pragma unroll
    for (int i = 0; i < 2; i++)
#pragma unroll
        for (int j = 0; j < 8; j++)
#pragma unroll
            for (int k = 0; k < 4; k++) acc[i][j][k] = 0.f;

    issue(0, 0);
    if (nIter > 1) issue(1, 1);

    for (int it = 0; it < nIter; it++) {
        if (it + 1 < nIter) { CP_WAIT1(); } else { CP_WAIT0(); }
        __syncthreads();

        uint32_t buf = sb + (it & 1) * (4 * GTB);

#pragma unroll
        for (int ks = 0; ks < 2; ks++) {
            const int kc = ks * 16;
            uint32_t ah[2][4], al[2][4];
            uint32_t a0 = buf + ((wm + arow_l) * SA + kc + acol_l) * 2;
            ldsm_x4(ah[0], a0);
            ldsm_x4(ah[1], a0 + 16 * SA * 2);
            ldsm_x4(al[0], a0 + GTB);
            ldsm_x4(al[1], a0 + GTB + 16 * SA * 2);

            uint32_t bhf[16], blf[16];
            uint32_t b0 = buf + 2 * GTB + ((wn + brow_l) * SA + kc + bcol_l) * 2;
#pragma unroll
            for (int p = 0; p < 4; p++) {
                ldsm_x4(&bhf[p * 4], b0 + p * 16 * SA * 2);
                ldsm_x4(&blf[p * 4], b0 + GTB + p * 16 * SA * 2);
            }
#pragma unroll
            for (int mt = 0; mt < 2; mt++)
#pragma unroll
                for (int nt = 0; nt < 8; nt++) {
                    mma16816(acc[mt][nt], ah[mt], &bhf[nt * 2]);
                    mma16816(acc[mt][nt], ah[mt], &blf[nt * 2]);
                    mma16816(acc[mt][nt], al[mt], &bhf[nt * 2]);
                }
        }
        __syncthreads();
        if (it + 2 < nIter) issue(it + 2, it & 1);
    }

    // ---- epilogue ----
#pragma unroll
    for (int mt = 0; mt < 2; mt++) {
        int r = bm + wm + mt * 16 + grp;
#pragma unroll
        for (int nt = 0; nt < 8; nt++) {
            int c = bn + wn + nt * 8 + qd;
            float a0 = acc[mt][nt][0], a1 = acc[mt][nt][1];
            float a2 = acc[mt][nt][2], a3 = acc[mt][nt][3];
            size_t i0 = (size_t)r * N + c;
            size_t i1 = (size_t)(r + 8) * N + c;
            if (mode == 0) {
                *(float2*)&Cf[i0] = make_float2(a0, a1);
                *(float2*)&Cf[i1] = make_float2(a2, a3);
            } else if (mode == 1) {
                store_split(Chi, Clo, i0, a0 * scale, a1 * scale);
                store_split(Chi, Clo, i1, a2 * scale, a3 * scale);
            } else {
                int d2 = (c & 63) >> 1;
                float c0 = cosv[r * 32 + d2],       s0 = sinv[r * 32 + d2];
                float c1 = cosv[(r + 8) * 32 + d2], s1 = sinv[(r + 8) * 32 + d2];
                float o0 = a0 * c0 - a1 * s0, o1 = a0 * s0 + a1 * c0;
                float o2 = a2 * c1 - a3 * s1, o3 = a2 * s1 + a3 * c1;
                if (mode == 3) {
                    *(float2*)&Cf[i0] = make_float2(o0, o1);
                    *(float2*)&Cf[i1] = make_float2(o2, o3);
                } else {
                    store_split(Chi, Clo, i0, o0, o1);
                    store_split(Chi, Clo, i1, o2, o3);
                }
            }
        }
    }
}

// ---------------------------------------------------------------------------
// Pipelined MMA flash attention (ldmatrix), causal GQA, split-bf16 x3.
// Grid (S/128, NH), 256 threads. Longest q-tiles scheduled first.
// ---------------------------------------------------------------------------
#define AST 72
#define ATB (64 * AST * 2)          // 9216
#define ATTN_SMEM (2 * 4 * ATB)     // 73728

__global__ __launch_bounds__(256) void attn_mma(
    const __nv_bfloat16* __restrict__ Qhi, const __nv_bfloat16* __restrict__ Qlo,
    const __nv_bfloat16* __restrict__ Khi, const __nv_bfloat16* __restrict__ Klo,
    const __nv_bfloat16* __restrict__ VThi, const __nv_bfloat16* __restrict__ VTlo,
    __nv_bfloat16* __restrict__ Yhi, __nv_bfloat16* __restrict__ Ylo) {

    extern __shared__ char dsm[];
    uint32_t sb = smem_u32(dsm);

    const int h    = blockIdx.y;
    const int kvh  = h >> 2;
    const int q0   = (gridDim.x - 1 - blockIdx.x) * 128;   // long tiles first
    const int tid  = threadIdx.x;
    const int lane = tid & 31;
    const int w    = tid >> 5;
    const int grp  = lane >> 2;
    const int qd   = (lane & 3) * 2;
    const int r0   = q0 + w * 16 + grp;

    const int brow_l = (lane & 7) + ((lane >> 4) << 3);
    const int bcol_l = ((lane >> 3) & 1) << 3;

    const int nChunks = (q0 >> 6) + 2;

    auto issueA = [&](int ci, int stage) {
        const int j0 = ci << 6;
        uint32_t base = sb + stage * (4 * ATB);
#pragma unroll
        for (int i = 0; i < 2; i++) {
            int c   = tid + i * 256;
            int row = c >> 3;
            int cb  = (c & 7) * 16;
            uint32_t so = row * (AST * 2) + cb;
            const char* g = (const char*)Khi + ((size_t)(j0 + row) * KVD + kvh * HD) * 2 + cb;
            CP_ASYNC16(base + so, g);
            g = (const char*)Klo + ((size_t)(j0 + row) * KVD + kvh * HD) * 2 + cb;
            CP_ASYNC16(base + ATB + so, g);
            g = (const char*)VThi + ((size_t)(kvh * HD + row) * S_LEN + j0) * 2 + cb;
            CP_ASYNC16(base + 2 * ATB + so, g);
            g = (const char*)VTlo + ((size_t)(kvh * HD + row) * S_LEN + j0) * 2 + cb;
            CP_ASYNC16(base + 3 * ATB + so, g);
        }
        CP_COMMIT();
    };

    // Q fragments, loaded once
    uint32_t qh[4][4], ql[4][4];
#pragma unroll
    for (int jk = 0; jk < 4; jk++) {
        size_t c0 = (size_t)r0 * D_MODEL + h * HD + jk * 16 + qd;
        size_t c1 = (size_t)(r0 + 8) * D_MODEL + h * HD + jk * 16 + qd;
        qh[jk][0] = *(const uint32_t*)&Qhi[c0];
        qh[jk][1] = *(const uint32_t*)&Qhi[c1];
        qh[jk][2] = *(const uint32_t*)&Qhi[c0 + 8];
        qh[jk][3] = *(const uint32_t*)&Qhi[c1 + 8];
        ql[jk][0] = *(const uint32_t*)&Qlo[c0];
        ql[jk][1] = *(const uint32_t*)&Qlo[c1];
        ql[jk][2] = *(const uint32_t*)&Qlo[c0 + 8];
        ql[jk][3] = *(const uint32_t*)&Qlo[c1 + 8];
    }

    float o[8][4];
#pragma unroll
    for (int nt = 0; nt < 8; nt++)
#pragma unroll
        for (int i = 0; i < 4; i++) o[nt][i] = 0.f;

    float m0 = -1e30f, m1 = -1e30f, l0 = 0.f, l1 = 0.f;

    issueA(0, 0);
    if (nChunks > 1) issueA(1, 1);

    for (int ci = 0; ci < nChunks; ci++) {
        const int j0 = ci << 6;
        if (ci + 1 < nChunks) { CP_WAIT1(); } else { CP_WAIT0(); }
        __syncthreads();

        uint32_t buf = sb + (ci & 1) * (4 * ATB);

        // S = Q K^T (x3)
        float s[8][4];
#pragma unroll
        for (int nt = 0; nt < 8; nt++)
#pragma unroll
            for (int i = 0; i < 4; i++) s[nt][i] = 0.f;

#pragma unroll
        for (int jk = 0; jk < 4; jk++) {
            uint32_t bhf[16], blf[16];
            uint32_t b0 = buf + (brow_l * AST + jk * 16 + bcol_l) * 2;
#pragma unroll
            for (int p = 0; p < 4; p++) {
                ldsm_x4(&bhf[p * 4], b0 + p * 16 * AST * 2);
                ldsm_x4(&blf[p * 4], b0 + ATB + p * 16 * AST * 2);
            }
#pragma unroll
            for (int nt = 0; nt < 8; nt++) {
                mma16816(s[nt], qh[jk], &bhf[nt * 2]);
                mma16816(s[nt], qh[jk], &blf[nt * 2]);
                mma16816(s[nt], ql[jk], &bhf[nt * 2]);
            }
        }

        if (ci >= nChunks - 2) {
#pragma unroll
            for (int nt = 0; nt < 8; nt++) {
                int col = j0 + nt * 8 + qd;
                if (col     > r0)     s[nt][0] = -1e30f;
                if (col + 1 > r0)     s[nt][1] = -1e30f;
                if (col     > r0 + 8) s[nt][2] = -1e30f;
                if (col + 1 > r0 + 8) s[nt][3] = -1e30f;
            }
        }

        float mx0 = -1e30f, mx1 = -1e30f;
#pragma unroll
        for (int nt = 0; nt < 8; nt++) {
            mx0 = fmaxf(mx0, fmaxf(s[nt][0], s[nt][1]));
            mx1 = fmaxf(mx1, fmaxf(s[nt][2], s[nt][3]));
        }
        mx0 = fmaxf(mx0, __shfl_xor_sync(0xffffffffu, mx0, 1));
        mx0 = fmaxf(mx0, __shfl_xor_sync(0xffffffffu, mx0, 2));
        mx1 = fmaxf(mx1, __shfl_xor_sync(0xffffffffu, mx1, 1));
        mx1 = fmaxf(mx1, __shfl_xor_sync(0xffffffffu, mx1, 2));

        float nm0 = fmaxf(m0, mx0), nm1 = fmaxf(m1, mx1);
        float corr0 = __expf(m0 - nm0), corr1 = __expf(m1 - nm1);

        uint32_t ph[4][4], pl[4][4];
        float sum0 = 0.f, sum1 = 0.f;
#pragma unroll
        for (int nt = 0; nt < 8; nt++) {
            float p0 = __expf(s[nt][0] - nm0), p1 = __expf(s[nt][1] - nm0);
            float p2 = __expf(s[nt][2] - nm1), p3 = __expf(s[nt][3] - nm1);
            sum0 += p0 + p1;
            sum1 += p2 + p3;
            uint32_t h01 = pack_bf16x2(p0, p1);
            uint32_t h23 = pack_bf16x2(p2, p3);
            float2 f01 = unpack_bf16x2(h01);
            float2 f23 = unpack_bf16x2(h23);
            uint32_t lo01 = pack_bf16x2(p0 - f01.x, p1 - f01.y);
            uint32_t lo23 = pack_bf16x2(p2 - f23.x, p3 - f23.y);
            int jk2 = nt >> 1, hf = (nt & 1) * 2;
            ph[jk2][hf]     = h01;
            ph[jk2][hf + 1] = h23;
            pl[jk2][hf]     = lo01;
            pl[jk2][hf + 1] = lo23;
        }
        sum0 += __shfl_xor_sync(0xffffffffu, sum0, 1);
        sum0 += __shfl_xor_sync(0xffffffffu, sum0, 2);
        sum1 += __shfl_xor_sync(0xffffffffu, sum1, 1);
        sum1 += __shfl_xor_sync(0xffffffffu, sum1, 2);
        l0 = l0 * corr0 + sum0;
        l1 = l1 * corr1 + sum1;
        m0 = nm0; m1 = nm1;

#pragma unroll
        for (int nt = 0; nt < 8; nt++) {
            o[nt][0] *= corr0; o[nt][1] *= corr0;
            o[nt][2] *= corr1; o[nt][3] *= corr1;
        }

        // O += P V (x3)
#pragma unroll
        for (int jk = 0; jk < 4; jk++) {
            uint32_t bhf[16], blf[16];
            uint32_t b0 = buf + 2 * ATB + (brow_l * AST + jk * 16 + bcol_l) * 2;
#pragma unroll
            for (int p = 0; p < 4; p++) {
                ldsm_x4(&bhf[p * 4], b0 + p * 16 * AST * 2);
                ldsm_x4(&blf[p * 4], b0 + ATB + p * 16 * AST * 2);
            }
#pragma unroll
            for (int nt = 0; nt < 8; nt++) {
                mma16816(o[nt], ph[jk], &bhf[nt * 2]);
                mma16816(o[nt], ph[jk], &blf[nt * 2]);
                mma16816(o[nt], pl[jk], &bhf[nt * 2]);
            }
        }

        __syncthreads();
        if (ci + 2 < nChunks) issueA(ci + 2, ci & 1);
    }

    float il0 = 1.f / l0, il1 = 1.f / l1;
#pragma unroll
    for (int nt = 0; nt < 8; nt++) {
        size_t c0 = (size_t)r0 * D_MODEL + h * HD + nt * 8 + qd;
        size_t c1 = (size_t)(r0 + 8) * D_MODEL + h * HD + nt * 8 + qd;
        store_split(Yhi, Ylo, c0, o[nt][0] * il0, o[nt][1] * il0);
        store_split(Yhi, Ylo, c1, o[nt][2] * il1, o[nt][3] * il1);
    }
}

// ---------------------------------------------------------------------------
extern "C" void kernel_launch(void* const* d_in, const int* in_sizes, int n_in,
                              void* d_out, int out_size) {
    const float* x    = (const float*)d_in[0];
    const float* tcos = (const float*)d_in[1];
    const float* tsin = (const float*)d_in[2];
    const float* wq   = (const float*)d_in[3];
    const float* wk   = (const float*)d_in[4];
    const float* wv   = (const float*)d_in[5];
    const float* wo   = (const float*)d_in[6];
    float* out = (float*)d_out;

    float* V;
    cudaGetSymbolAddress((void**)&V, g_V);

    __nv_bfloat16 *xhi, *xlo, *yhi, *ylo, *qhi, *qlo, *khi, *klo, *vthi, *vtlo;
    __nv_bfloat16 *wqThi, *wqTlo, *wkThi, *wkTlo, *wvThi, *wvTlo, *woThi, *woTlo;
    cudaGetSymbolAddress((void**)&xhi, g_xhi);   cudaGetSymbolAddress((void**)&xlo, g_xlo);
    cudaGetSymbolAddress((void**)&yhi, g_yhi);   cudaGetSymbolAddress((void**)&ylo, g_ylo);
    cudaGetSymbolAddress((void**)&qhi, g_qhi);   cudaGetSymbolAddress((void**)&qlo, g_qlo);
    cudaGetSymbolAddress((void**)&khi, g_khi);   cudaGetSymbolAddress((void**)&klo, g_klo);
    cudaGetSymbolAddress((void**)&vthi, g_vthi); cudaGetSymbolAddress((void**)&vtlo, g_vtlo);
    cudaGetSymbolAddress((void**)&wqThi, g_wqT_hi); cudaGetSymbolAddress((void**)&wqTlo, g_wqT_lo);
    cudaGetSymbolAddress((void**)&wkThi, g_wkT_hi); cudaGetSymbolAddress((void**)&wkTlo, g_wkT_lo);
    cudaGetSymbolAddress((void**)&wvThi, g_wvT_hi); cudaGetSymbolAddress((void**)&wvTlo, g_wvT_lo);
    cudaGetSymbolAddress((void**)&woThi, g_woT_hi); cudaGetSymbolAddress((void**)&woTlo, g_woT_lo);

    cudaFuncSetAttribute(gemm_mma_x3, cudaFuncAttributeMaxDynamicSharedMemorySize, GEMM_SMEM);
    cudaFuncSetAttribute(attn_mma,    cudaFuncAttributeMaxDynamicSharedMemorySize, ATTN_SMEM);

    const int nx = S_LEN * D_MODEL;

    // Split x into bf16 hi/lo
    split_kernel<<<(nx + 255) / 256, 256>>>(x, xhi, xlo, nx, 1.0f);

    // Transpose+split weights: W[K][N] -> WT[N][K]
    transpose_split_kernel<<<dim3(D_MODEL / 32, D_MODEL / 32), dim3(32, 8)>>>(wq, wqThi, wqTlo, D_MODEL, D_MODEL);
    transpose_split_kernel<<<dim3(KVD / 32,     D_MODEL / 32), dim3(32, 8)>>>(wk, wkThi, wkTlo, D_MODEL, KVD);
    transpose_split_kernel<<<dim3(KVD / 32,     D_MODEL / 32), dim3(32, 8)>>>(wv, wvThi, wvTlo, D_MODEL, KVD);
    transpose_split_kernel<<<dim3(D_MODEL / 32, D_MODEL / 32), dim3(32, 8)>>>(wo, woThi, woTlo, D_MODEL, D_MODEL);

    // Q projection: fused scale + bf16 split epilogue
    gemm_mma_x3<<<dim3(D_MODEL / 128, S_LEN / 128), 256, GEMM_SMEM>>>(
        xhi, xlo, wqThi, wqTlo, nullptr, qhi, qlo, nullptr, nullptr,
        D_MODEL, D_MODEL, 1, 0.125f);
    // K projection: fused RoPE + bf16 split epilogue
    gemm_mma_x3<<<dim3(KVD / 128, S_LEN / 128), 256, GEMM_SMEM>>>(
        xhi, xlo, wkThi, wkTlo, nullptr, khi, klo, tcos, tsin,
        KVD, D_MODEL, 2, 1.0f);
    // V projection: fused RoPE, fp32 out (then transposed)
    gemm_mma_x3<<<dim3(KVD / 128, S_LEN / 128), 256, GEMM_SMEM>>>(
        xhi, xlo, wvThi, wvTlo, V, nullptr, nullptr, tcos, tsin,
        KVD, D_MODEL, 3, 1.0f);

    // V transpose+split for attention ([dim][seq])
    transpose_split_kernel<<<dim3(KVD / 32, S_LEN / 32), dim3(32, 8)>>>(V, vthi, vtlo, S_LEN, KVD);

    // MMA flash attention -> Yhi/Ylo
    attn_mma<<<dim3(S_LEN / 128, NH), 256, ATTN_SMEM>>>(qhi, qlo, khi, klo, vthi, vtlo, yhi, ylo);

    // Output projection (fp32 out)
    gemm_mma_x3<<<dim3(D_MODEL / 128, S_LEN / 128), 256, GEMM_SMEM>>>(
        yhi, ylo, woThi, woTlo, out, nullptr, nullptr, nullptr, nullptr,
        D_MODEL, D_MODEL, 0, 1.0f);
}